// round 1
// baseline (speedup 1.0000x reference)
#include <cuda_runtime.h>
#include <cuda_bf16.h>
#include <math.h>

// ---------------- problem constants ----------------
#define E_NUM      8
#define TOPK       2
#define IN_D       1024
#define HD         2048
#define NTOK       16384          // BS*SEQ = 8*2048
#define NK         32768          // NTOK*TOPK
#define CAP        5120           // ceil(ceil(NK/E)*1.25)
#define ROUTE_BLOCKS 2048         // NTOK / 8 tokens per block

// ---------------- device scratch (no allocations allowed) ----------------
__device__ float g_h[(size_t)E_NUM * CAP * HD];        // 335 MB: SwiGLU hidden
__device__ float g_buf_out[(size_t)E_NUM * CAP * IN_D];// 168 MB: expert outputs
__device__ int   g_exp[NK];
__device__ float g_w[NK];
__device__ int   g_slot[NK];
__device__ int   g_slot_token[E_NUM * CAP];
__device__ int   g_counts[E_NUM];
__device__ int   g_kept[E_NUM];
__device__ float g_prob_part[ROUTE_BLOCKS * E_NUM];

// ============================================================
// 1) routing: logits, softmax, top-2, per-block prob partial sums
//    one warp per token, 8 warps per block
// ============================================================
__global__ __launch_bounds__(256) void route_kernel(const float* __restrict__ x,
                                                    const float* __restrict__ gate_w)
{
    __shared__ float sg[E_NUM * IN_D];   // 32KB
    __shared__ float pp[8][E_NUM];
    for (int i = threadIdx.x; i < E_NUM * IN_D; i += blockDim.x) sg[i] = gate_w[i];
    __syncthreads();

    int w    = threadIdx.x >> 5;
    int lane = threadIdx.x & 31;
    int t    = blockIdx.x * 8 + w;

    const float* xr = x + (size_t)t * IN_D;
    float acc[E_NUM];
#pragma unroll
    for (int e = 0; e < E_NUM; e++) acc[e] = 0.f;

    for (int j = 0; j < IN_D / 32; j++) {
        float xv = xr[lane + j * 32];
#pragma unroll
        for (int e = 0; e < E_NUM; e++)
            acc[e] += xv * sg[e * IN_D + lane + j * 32];
    }
#pragma unroll
    for (int off = 16; off > 0; off >>= 1) {
#pragma unroll
        for (int e = 0; e < E_NUM; e++)
            acc[e] += __shfl_down_sync(0xffffffffu, acc[e], off);
    }

    if (lane == 0) {
        float m = acc[0];
#pragma unroll
        for (int e = 1; e < E_NUM; e++) m = fmaxf(m, acc[e]);
        float p[E_NUM], s = 0.f;
#pragma unroll
        for (int e = 0; e < E_NUM; e++) { p[e] = expf(acc[e] - m); s += p[e]; }
        float inv = 1.f / s;
#pragma unroll
        for (int e = 0; e < E_NUM; e++) p[e] *= inv;

        // top-2, ties -> lowest index (strict > keeps first max), matches lax.top_k
        int e1 = 0;
#pragma unroll
        for (int e = 1; e < E_NUM; e++) if (p[e] > p[e1]) e1 = e;
        int e2 = (e1 == 0) ? 1 : 0;
#pragma unroll
        for (int e = 0; e < E_NUM; e++) if (e != e1 && p[e] > p[e2]) e2 = e;

        float denom = p[e1] + p[e2] + 1e-9f;
        g_exp[2 * t]     = e1;
        g_exp[2 * t + 1] = e2;
        g_w[2 * t]       = p[e1] / denom;
        g_w[2 * t + 1]   = p[e2] / denom;
#pragma unroll
        for (int e = 0; e < E_NUM; e++) pp[w][e] = p[e];
    }
    __syncthreads();
    if (threadIdx.x < E_NUM) {
        float s = 0.f;
        for (int ww = 0; ww < 8; ww++) s += pp[ww][threadIdx.x];
        g_prob_part[blockIdx.x * E_NUM + threadIdx.x] = s;
    }
}

// ============================================================
// 2) dispatch: stable-order per-expert positions + capacity drop
//    single block, 1024 threads, 32 items each
// ============================================================
__global__ __launch_bounds__(1024) void dispatch_kernel()
{
    __shared__ int sc[1024 * E_NUM];   // 32KB
    int tid  = threadIdx.x;
    int base = tid * 32;

    int h[E_NUM];
#pragma unroll
    for (int e = 0; e < E_NUM; e++) h[e] = 0;
    for (int i = 0; i < 32; i++) h[g_exp[base + i]]++;
#pragma unroll
    for (int e = 0; e < E_NUM; e++) sc[tid * E_NUM + e] = h[e];
    __syncthreads();

    // inclusive scan across tids (doubling)
    for (int off = 1; off < 1024; off <<= 1) {
        int v[E_NUM];
        if (tid >= off) {
#pragma unroll
            for (int e = 0; e < E_NUM; e++) v[e] = sc[(tid - off) * E_NUM + e];
        }
        __syncthreads();
        if (tid >= off) {
#pragma unroll
            for (int e = 0; e < E_NUM; e++) sc[tid * E_NUM + e] += v[e];
        }
        __syncthreads();
    }

    int basec[E_NUM];
#pragma unroll
    for (int e = 0; e < E_NUM; e++) basec[e] = sc[tid * E_NUM + e] - h[e];

    if (tid == 1023) {
#pragma unroll
        for (int e = 0; e < E_NUM; e++) {
            int c = sc[tid * E_NUM + e];
            g_counts[e] = c;
            g_kept[e]   = (c < CAP) ? c : CAP;
        }
    }

    for (int i = 0; i < 32; i++) {
        int idx = base + i;
        int e   = g_exp[idx];
        int pos = basec[e]++;
        if (pos < CAP) {
            int s = e * CAP + pos;
            g_slot[idx]     = s;
            g_slot_token[s] = idx >> 1;   // token index (x repeated K times)
        } else {
            g_slot[idx] = -1;
        }
    }
}

// ============================================================
// 3) balancing loss (deterministic reduction)
// ============================================================
__global__ void loss_kernel(float* out_loss)
{
    __shared__ float ps[E_NUM];
    if (threadIdx.x < E_NUM) {
        float s = 0.f;
        for (int b = 0; b < ROUTE_BLOCKS; b++) s += g_prob_part[b * E_NUM + threadIdx.x];
        float p = s / (float)NTOK;
        float f = (float)g_counts[threadIdx.x] / (float)NK;
        ps[threadIdx.x] = p * f;
    }
    __syncthreads();
    if (threadIdx.x == 0 && out_loss) {
        float s = 0.f;
#pragma unroll
        for (int e = 0; e < E_NUM; e++) s += ps[e];
        *out_loss = (float)E_NUM * s;
    }
}

// ============================================================
// 4) GEMM1 fused: h = silu(Xg . fc1^T) * (Xg . gating^T)
//    tile 128x64, BK=16, 256 threads, 8x4 micro-tile, dual accumulators
// ============================================================
#define BM 128
#define BN 64
#define BK 16

__global__ __launch_bounds__(256, 2) void gemm1_kernel(const float* __restrict__ x,
                                                       const float* __restrict__ fc1,
                                                       const float* __restrict__ gating)
{
    int e    = blockIdx.z;
    int kept = g_kept[e];
    int m0   = blockIdx.x * BM;
    if (m0 >= kept) return;
    int n0   = blockIdx.y * BN;

    __shared__ float sA[BK][BM];
    __shared__ float sB1[BK][BN];
    __shared__ float sB2[BK][BN];

    int tid = threadIdx.x;
    int tx  = tid & 15;        // n micro (4 cols)
    int ty  = tid >> 4;        // m micro (8 rows)

    // A loads: 128 rows x 16 cols = 512 float4; 2 per thread
    int ar = tid >> 2;          // 0..63 (and +64)
    int ak = (tid & 3) * 4;
    const float* aptr[2];
#pragma unroll
    for (int i = 0; i < 2; i++) {
        int r = m0 + ar + i * 64;
        if (r < kept) {
            int tok = g_slot_token[e * CAP + r];
            aptr[i] = x + (size_t)tok * IN_D;
        } else {
            aptr[i] = nullptr;
        }
    }
    // B loads: 64 rows x 16 cols = 256 float4; 1 per thread per matrix
    int br = tid >> 2;
    int bk = (tid & 3) * 4;
    const float* b1p = fc1    + ((size_t)e * HD + n0 + br) * IN_D + bk;
    const float* b2p = gating + ((size_t)e * HD + n0 + br) * IN_D + bk;

    float acc1[8][4], acc2[8][4];
#pragma unroll
    for (int i = 0; i < 8; i++)
#pragma unroll
        for (int j = 0; j < 4; j++) { acc1[i][j] = 0.f; acc2[i][j] = 0.f; }

    float4 av0 = aptr[0] ? *(const float4*)(aptr[0] + ak) : make_float4(0, 0, 0, 0);
    float4 av1 = aptr[1] ? *(const float4*)(aptr[1] + ak) : make_float4(0, 0, 0, 0);
    float4 bv1 = *(const float4*)(b1p);
    float4 bv2 = *(const float4*)(b2p);

    for (int k0 = 0; k0 < IN_D; k0 += BK) {
        __syncthreads();
        sA[ak + 0][ar]      = av0.x; sA[ak + 1][ar]      = av0.y;
        sA[ak + 2][ar]      = av0.z; sA[ak + 3][ar]      = av0.w;
        sA[ak + 0][ar + 64] = av1.x; sA[ak + 1][ar + 64] = av1.y;
        sA[ak + 2][ar + 64] = av1.z; sA[ak + 3][ar + 64] = av1.w;
        sB1[bk + 0][br] = bv1.x; sB1[bk + 1][br] = bv1.y;
        sB1[bk + 2][br] = bv1.z; sB1[bk + 3][br] = bv1.w;
        sB2[bk + 0][br] = bv2.x; sB2[bk + 1][br] = bv2.y;
        sB2[bk + 2][br] = bv2.z; sB2[bk + 3][br] = bv2.w;
        __syncthreads();

        int kn = k0 + BK;
        if (kn < IN_D) {  // prefetch next tile (overlaps with compute below)
            av0 = aptr[0] ? *(const float4*)(aptr[0] + kn + ak) : make_float4(0, 0, 0, 0);
            av1 = aptr[1] ? *(const float4*)(aptr[1] + kn + ak) : make_float4(0, 0, 0, 0);
            bv1 = *(const float4*)(b1p + kn);
            bv2 = *(const float4*)(b2p + kn);
        }

#pragma unroll
        for (int kk = 0; kk < BK; kk++) {
            float a[8], b1[4], b2[4];
            *(float4*)&a[0] = *(float4*)&sA[kk][ty * 8];
            *(float4*)&a[4] = *(float4*)&sA[kk][ty * 8 + 4];
            *(float4*)&b1[0] = *(float4*)&sB1[kk][tx * 4];
            *(float4*)&b2[0] = *(float4*)&sB2[kk][tx * 4];
#pragma unroll
            for (int i = 0; i < 8; i++)
#pragma unroll
                for (int j = 0; j < 4; j++) {
                    acc1[i][j] = fmaf(a[i], b1[j], acc1[i][j]);
                    acc2[i][j] = fmaf(a[i], b2[j], acc2[i][j]);
                }
        }
    }

    // epilogue: SwiGLU
#pragma unroll
    for (int i = 0; i < 8; i++) {
        int r = m0 + ty * 8 + i;
        if (r < kept) {
            float* hrow = g_h + (size_t)(e * CAP + r) * HD + n0 + tx * 4;
#pragma unroll
            for (int j = 0; j < 4; j++) {
                float v1 = acc1[i][j];
                float v2 = acc2[i][j];
                hrow[j] = v1 / (1.f + expf(-v1)) * v2;
            }
        }
    }
}

// ============================================================
// 5) GEMM2: out = H . fc2^T   (K = HD = 2048, N = IN_D = 1024)
// ============================================================
__global__ __launch_bounds__(256, 2) void gemm2_kernel(const float* __restrict__ fc2)
{
    int e    = blockIdx.z;
    int kept = g_kept[e];
    int m0   = blockIdx.x * BM;
    if (m0 >= kept) return;
    int n0   = blockIdx.y * BN;

    __shared__ float sA[BK][BM];
    __shared__ float sB[BK][BN];

    int tid = threadIdx.x;
    int tx  = tid & 15;
    int ty  = tid >> 4;

    int ar = tid >> 2;
    int ak = (tid & 3) * 4;
    const float* ap0 = g_h + (size_t)(e * CAP + m0 + ar) * HD + ak;       // rows in-bounds (<CAP)
    const float* ap1 = g_h + (size_t)(e * CAP + m0 + ar + 64) * HD + ak;

    int br = tid >> 2;
    int bk = (tid & 3) * 4;
    const float* bp = fc2 + ((size_t)e * IN_D + n0 + br) * HD + bk;

    float acc[8][4];
#pragma unroll
    for (int i = 0; i < 8; i++)
#pragma unroll
        for (int j = 0; j < 4; j++) acc[i][j] = 0.f;

    float4 av0 = *(const float4*)(ap0);
    float4 av1 = *(const float4*)(ap1);
    float4 bv  = *(const float4*)(bp);

    for (int k0 = 0; k0 < HD; k0 += BK) {
        __syncthreads();
        sA[ak + 0][ar]      = av0.x; sA[ak + 1][ar]      = av0.y;
        sA[ak + 2][ar]      = av0.z; sA[ak + 3][ar]      = av0.w;
        sA[ak + 0][ar + 64] = av1.x; sA[ak + 1][ar + 64] = av1.y;
        sA[ak + 2][ar + 64] = av1.z; sA[ak + 3][ar + 64] = av1.w;
        sB[bk + 0][br] = bv.x; sB[bk + 1][br] = bv.y;
        sB[bk + 2][br] = bv.z; sB[bk + 3][br] = bv.w;
        __syncthreads();

        int kn = k0 + BK;
        if (kn < HD) {
            av0 = *(const float4*)(ap0 + kn);
            av1 = *(const float4*)(ap1 + kn);
            bv  = *(const float4*)(bp + kn);
        }

#pragma unroll
        for (int kk = 0; kk < BK; kk++) {
            float a[8], b[4];
            *(float4*)&a[0] = *(float4*)&sA[kk][ty * 8];
            *(float4*)&a[4] = *(float4*)&sA[kk][ty * 8 + 4];
            *(float4*)&b[0] = *(float4*)&sB[kk][tx * 4];
#pragma unroll
            for (int i = 0; i < 8; i++)
#pragma unroll
                for (int j = 0; j < 4; j++)
                    acc[i][j] = fmaf(a[i], b[j], acc[i][j]);
        }
    }

#pragma unroll
    for (int i = 0; i < 8; i++) {
        int r = m0 + ty * 8 + i;
        if (r < kept) {
            float* orow = g_buf_out + (size_t)(e * CAP + r) * IN_D + n0 + tx * 4;
            *(float4*)orow = make_float4(acc[i][0], acc[i][1], acc[i][2], acc[i][3]);
        }
    }
}

// ============================================================
// 6) combine: out[t] = w1*buf[s1] + w2*buf[s2]
// ============================================================
__global__ __launch_bounds__(256) void combine_kernel(float* __restrict__ out)
{
    int t  = blockIdx.x;
    int s1 = g_slot[2 * t];
    int s2 = g_slot[2 * t + 1];
    float w1 = (s1 >= 0) ? g_w[2 * t]     : 0.f;
    float w2 = (s2 >= 0) ? g_w[2 * t + 1] : 0.f;
    const float4* r1 = (s1 >= 0) ? (const float4*)(g_buf_out + (size_t)s1 * IN_D) : nullptr;
    const float4* r2 = (s2 >= 0) ? (const float4*)(g_buf_out + (size_t)s2 * IN_D) : nullptr;

    int d = threadIdx.x;   // 256 threads x float4 = 1024 floats
    float4 v = make_float4(0, 0, 0, 0);
    if (r1) {
        float4 a = r1[d];
        v.x += w1 * a.x; v.y += w1 * a.y; v.z += w1 * a.z; v.w += w1 * a.w;
    }
    if (r2) {
        float4 a = r2[d];
        v.x += w2 * a.x; v.y += w2 * a.y; v.z += w2 * a.z; v.w += w2 * a.w;
    }
    ((float4*)(out + (size_t)t * IN_D))[d] = v;
}

// ============================================================
extern "C" void kernel_launch(void* const* d_in, const int* in_sizes, int n_in,
                              void* d_out, int out_size)
{
    const float* x      = (const float*)d_in[0];
    const float* gate_w = (const float*)d_in[1];
    const float* fc1_w  = (const float*)d_in[2];
    const float* gating = (const float*)d_in[3];
    const float* fc2_w  = (const float*)d_in[4];
    float* out = (float*)d_out;

    float* loss_ptr = (out_size > NTOK * IN_D) ? out + (size_t)NTOK * IN_D : nullptr;

    route_kernel<<<ROUTE_BLOCKS, 256>>>(x, gate_w);
    dispatch_kernel<<<1, 1024>>>();
    loss_kernel<<<1, 32>>>(loss_ptr);
    gemm1_kernel<<<dim3(CAP / BM, HD / BN, E_NUM), 256>>>(x, fc1_w, gating);
    gemm2_kernel<<<dim3(CAP / BM, IN_D / BN, E_NUM), 256>>>(fc2_w);
    combine_kernel<<<NTOK, 256>>>(out);
}

// round 3
// speedup vs baseline: 2.3069x; 2.3069x over previous
#include <cuda_runtime.h>
#include <cuda_bf16.h>
#include <cstdint>
#include <math.h>

// ---------------- problem constants ----------------
#define E_NUM      8
#define TOPK       2
#define IN_D       1024
#define HD         2048
#define NTOK       16384
#define NK         32768
#define CAP        5120
#define ROUTE_BLOCKS 2048

// ---------------- device scratch ----------------
__device__ __nv_bfloat16 g_xhi[(size_t)NTOK * IN_D];
__device__ __nv_bfloat16 g_xlo[(size_t)NTOK * IN_D];
__device__ __nv_bfloat16 g_w1hi[(size_t)E_NUM * HD * IN_D];
__device__ __nv_bfloat16 g_w1lo[(size_t)E_NUM * HD * IN_D];
__device__ __nv_bfloat16 g_wghi[(size_t)E_NUM * HD * IN_D];
__device__ __nv_bfloat16 g_wglo[(size_t)E_NUM * HD * IN_D];
__device__ __nv_bfloat16 g_w2hi[(size_t)E_NUM * IN_D * HD];
__device__ __nv_bfloat16 g_w2lo[(size_t)E_NUM * IN_D * HD];
__device__ __nv_bfloat16 g_hhi[(size_t)E_NUM * CAP * HD];
__device__ __nv_bfloat16 g_hlo[(size_t)E_NUM * CAP * HD];
__device__ float g_buf_out[(size_t)E_NUM * CAP * IN_D];
__device__ int   g_exp[NK];
__device__ float g_w[NK];
__device__ int   g_slot[NK];
__device__ int   g_slot_token[E_NUM * CAP];
__device__ int   g_counts[E_NUM];
__device__ int   g_kept[E_NUM];
__device__ float g_prob_part[ROUTE_BLOCKS * E_NUM];

// ---------------- PTX helpers (all legal on compute_103) ----------------
__device__ __forceinline__ uint32_t smem_u32(const void* p) {
    uint32_t a;
    asm("{ .reg .u64 t; cvta.to.shared.u64 t, %1; cvt.u32.u64 %0, t; }" : "=r"(a) : "l"(p));
    return a;
}

#define CPA16(dst, src) \
    asm volatile("cp.async.cg.shared.global [%0], [%1], 16;" :: "r"(dst), "l"(src) : "memory")

#define LDSM4(r, addr) \
    asm volatile("ldmatrix.sync.aligned.m8n8.x4.shared.b16 {%0,%1,%2,%3}, [%4];" \
        : "=r"((r)[0]), "=r"((r)[1]), "=r"((r)[2]), "=r"((r)[3]) : "r"(addr))

#define MMA_BF16(d, a, bb) \
    asm volatile("mma.sync.aligned.m16n8k16.row.col.f32.bf16.bf16.f32 " \
        "{%0,%1,%2,%3}, {%4,%5,%6,%7}, {%8,%9}, {%0,%1,%2,%3};" \
        : "+f"((d)[0]), "+f"((d)[1]), "+f"((d)[2]), "+f"((d)[3]) \
        : "r"((a)[0]), "r"((a)[1]), "r"((a)[2]), "r"((a)[3]), \
          "r"((bb)[0]), "r"((bb)[1]))

// ============================================================
// 0) fp32 -> (bf16 hi, bf16 lo) split
// ============================================================
__global__ __launch_bounds__(256) void split_kernel(const float4* __restrict__ in,
                                                    int which, int n4)
{
    __nv_bfloat16 *hi, *lo;
    switch (which) {
        case 0: hi = g_xhi;  lo = g_xlo;  break;
        case 1: hi = g_w1hi; lo = g_w1lo; break;
        case 2: hi = g_wghi; lo = g_wglo; break;
        default: hi = g_w2hi; lo = g_w2lo; break;
    }
    uint2* hi4 = (uint2*)hi;
    uint2* lo4 = (uint2*)lo;
    for (int i = blockIdx.x * blockDim.x + threadIdx.x; i < n4;
         i += gridDim.x * blockDim.x) {
        float4 v = in[i];
        __nv_bfloat16 hx = __float2bfloat16(v.x), hy = __float2bfloat16(v.y);
        __nv_bfloat16 hz = __float2bfloat16(v.z), hw = __float2bfloat16(v.w);
        __nv_bfloat16 lx = __float2bfloat16(v.x - __bfloat162float(hx));
        __nv_bfloat16 ly = __float2bfloat16(v.y - __bfloat162float(hy));
        __nv_bfloat16 lz = __float2bfloat16(v.z - __bfloat162float(hz));
        __nv_bfloat16 lw = __float2bfloat16(v.w - __bfloat162float(hw));
        __nv_bfloat162 h01 = __halves2bfloat162(hx, hy), h23 = __halves2bfloat162(hz, hw);
        __nv_bfloat162 l01 = __halves2bfloat162(lx, ly), l23 = __halves2bfloat162(lz, lw);
        uint2 ho, lo2;
        ho.x = *reinterpret_cast<uint32_t*>(&h01);
        ho.y = *reinterpret_cast<uint32_t*>(&h23);
        lo2.x = *reinterpret_cast<uint32_t*>(&l01);
        lo2.y = *reinterpret_cast<uint32_t*>(&l23);
        hi4[i] = ho;
        lo4[i] = lo2;
    }
}

// ============================================================
// 1) routing
// ============================================================
__global__ __launch_bounds__(256) void route_kernel(const float* __restrict__ x,
                                                    const float* __restrict__ gate_w)
{
    __shared__ float sg[E_NUM * IN_D];
    __shared__ float pp[8][E_NUM];
    for (int i = threadIdx.x; i < E_NUM * IN_D; i += blockDim.x) sg[i] = gate_w[i];
    __syncthreads();

    int w = threadIdx.x >> 5, lane = threadIdx.x & 31;
    int t = blockIdx.x * 8 + w;
    const float* xr = x + (size_t)t * IN_D;
    float acc[E_NUM];
#pragma unroll
    for (int e = 0; e < E_NUM; e++) acc[e] = 0.f;
    for (int j = 0; j < IN_D / 32; j++) {
        float xv = xr[lane + j * 32];
#pragma unroll
        for (int e = 0; e < E_NUM; e++) acc[e] += xv * sg[e * IN_D + lane + j * 32];
    }
#pragma unroll
    for (int off = 16; off > 0; off >>= 1)
#pragma unroll
        for (int e = 0; e < E_NUM; e++) acc[e] += __shfl_down_sync(0xffffffffu, acc[e], off);

    if (lane == 0) {
        float m = acc[0];
#pragma unroll
        for (int e = 1; e < E_NUM; e++) m = fmaxf(m, acc[e]);
        float p[E_NUM], s = 0.f;
#pragma unroll
        for (int e = 0; e < E_NUM; e++) { p[e] = expf(acc[e] - m); s += p[e]; }
        float inv = 1.f / s;
#pragma unroll
        for (int e = 0; e < E_NUM; e++) p[e] *= inv;
        int e1 = 0;
#pragma unroll
        for (int e = 1; e < E_NUM; e++) if (p[e] > p[e1]) e1 = e;
        int e2 = (e1 == 0) ? 1 : 0;
#pragma unroll
        for (int e = 0; e < E_NUM; e++) if (e != e1 && p[e] > p[e2]) e2 = e;
        float denom = p[e1] + p[e2] + 1e-9f;
        g_exp[2 * t] = e1; g_exp[2 * t + 1] = e2;
        g_w[2 * t] = p[e1] / denom; g_w[2 * t + 1] = p[e2] / denom;
#pragma unroll
        for (int e = 0; e < E_NUM; e++) pp[w][e] = p[e];
    }
    __syncthreads();
    if (threadIdx.x < E_NUM) {
        float s = 0.f;
        for (int ww = 0; ww < 8; ww++) s += pp[ww][threadIdx.x];
        g_prob_part[blockIdx.x * E_NUM + threadIdx.x] = s;
    }
}

// ============================================================
// 2) dispatch
// ============================================================
__global__ __launch_bounds__(1024) void dispatch_kernel()
{
    __shared__ int sc[1024 * E_NUM];
    int tid = threadIdx.x, base = tid * 32;
    int h[E_NUM];
#pragma unroll
    for (int e = 0; e < E_NUM; e++) h[e] = 0;
    for (int i = 0; i < 32; i++) h[g_exp[base + i]]++;
#pragma unroll
    for (int e = 0; e < E_NUM; e++) sc[tid * E_NUM + e] = h[e];
    __syncthreads();
    for (int off = 1; off < 1024; off <<= 1) {
        int v[E_NUM];
        if (tid >= off)
#pragma unroll
            for (int e = 0; e < E_NUM; e++) v[e] = sc[(tid - off) * E_NUM + e];
        __syncthreads();
        if (tid >= off)
#pragma unroll
            for (int e = 0; e < E_NUM; e++) sc[tid * E_NUM + e] += v[e];
        __syncthreads();
    }
    int basec[E_NUM];
#pragma unroll
    for (int e = 0; e < E_NUM; e++) basec[e] = sc[tid * E_NUM + e] - h[e];
    if (tid == 1023)
#pragma unroll
        for (int e = 0; e < E_NUM; e++) {
            int c = sc[tid * E_NUM + e];
            g_counts[e] = c;
            g_kept[e] = (c < CAP) ? c : CAP;
        }
    for (int i = 0; i < 32; i++) {
        int idx = base + i;
        int e = g_exp[idx];
        int pos = basec[e]++;
        if (pos < CAP) {
            int s = e * CAP + pos;
            g_slot[idx] = s;
            g_slot_token[s] = idx >> 1;
        } else g_slot[idx] = -1;
    }
}

// ============================================================
// 3) loss
// ============================================================
__global__ void loss_kernel(float* out_loss)
{
    __shared__ float ps[E_NUM];
    if (threadIdx.x < E_NUM) {
        float s = 0.f;
        for (int b = 0; b < ROUTE_BLOCKS; b++) s += g_prob_part[b * E_NUM + threadIdx.x];
        float p = s / (float)NTOK;
        float f = (float)g_counts[threadIdx.x] / (float)NK;
        ps[threadIdx.x] = p * f;
    }
    __syncthreads();
    if (threadIdx.x == 0 && out_loss) {
        float s = 0.f;
#pragma unroll
        for (int e = 0; e < E_NUM; e++) s += ps[e];
        *out_loss = (float)E_NUM * s;
    }
}

// ============================================================
// GEMM tiling constants
// tile 128x128, BK=32, 8 warps (warp tile 64x32), bf16x3 mma.sync
// smem rows padded to 80B: conflict-free ldmatrix
// ============================================================
#define LDSROW 80
#define CSZ    (128 * LDSROW)   // 10240 B per component tile

// ============================================================
// 4) GEMM1: h = silu(Xg . fc1^T) * (Xg . gating^T), K = 1024
// ============================================================
__global__ __launch_bounds__(256, 1) void gemm1_mma()
{
    extern __shared__ char smem[];
    int e = blockIdx.z;
    int kept = g_kept[e];
    int m0 = blockIdx.x * 128;
    if (m0 >= kept) return;
    int n0 = blockIdx.y * 128;

    uint32_t sb = smem_u32(smem);
    int tid = threadIdx.x, lane = tid & 31, wid = tid >> 5;
    int wm = wid & 1, wn = wid >> 1;

    // --- loader setup: 2 chunks/thread/component, 6 components ---
    const __nv_bfloat16* gsrc[12];
    uint32_t sdst[12];
#pragma unroll
    for (int ci = 0; ci < 2; ci++) {
        int c = tid + ci * 256;
        int row = c >> 2, kc = c & 3;
        int tok = g_slot_token[e * CAP + m0 + row] & (NTOK - 1);
        size_t ar = (size_t)tok * IN_D + kc * 8;
        size_t br = ((size_t)e * HD + n0 + row) * IN_D + kc * 8;
        gsrc[ci * 6 + 0] = g_xhi + ar;
        gsrc[ci * 6 + 1] = g_xlo + ar;
        gsrc[ci * 6 + 2] = g_w1hi + br;
        gsrc[ci * 6 + 3] = g_w1lo + br;
        gsrc[ci * 6 + 4] = g_wghi + br;
        gsrc[ci * 6 + 5] = g_wglo + br;
        uint32_t sd = sb + row * LDSROW + kc * 16;
#pragma unroll
        for (int comp = 0; comp < 6; comp++) sdst[ci * 6 + comp] = sd + comp * CSZ;
    }

    const int STG = 6 * CSZ;   // 61440 per stage, 3 stages
    auto load_stage = [&](int slab, int st) {
        int ko = slab * 32;
        uint32_t so = st * STG;
#pragma unroll
        for (int i = 0; i < 12; i++) CPA16(sdst[i] + so, gsrc[i] + ko);
        asm volatile("cp.async.commit_group;" ::: "memory");
    };
    load_stage(0, 0);
    load_stage(1, 1);
    load_stage(2, 2);

    // --- ldmatrix lane offsets ---
    uint32_t a_off[4], b_off[2];
#pragma unroll
    for (int mi = 0; mi < 4; mi++)
        a_off[mi] = (wm * 64 + mi * 16 + (lane & 15)) * LDSROW + (lane >> 4) * 16;
#pragma unroll
    for (int ni = 0; ni < 2; ni++)
        b_off[ni] = (wn * 32 + ni * 16 + (lane & 7) + ((lane >> 4) << 3)) * LDSROW
                    + ((lane >> 3) & 1) * 16;

    float acc1[4][4][4], acc2[4][4][4];
#pragma unroll
    for (int mi = 0; mi < 4; mi++)
#pragma unroll
        for (int nj = 0; nj < 4; nj++)
#pragma unroll
            for (int q = 0; q < 4; q++) { acc1[mi][nj][q] = 0.f; acc2[mi][nj][q] = 0.f; }

    for (int s = 0; s < 32; s++) {
        int st = s % 3;
        if (s < 29) asm volatile("cp.async.wait_group 2;" ::: "memory");
        else        asm volatile("cp.async.wait_group 0;" ::: "memory");
        __syncthreads();
        uint32_t base = sb + st * STG;
#pragma unroll
        for (int ks = 0; ks < 2; ks++) {
            uint32_t kb = ks * 32;
            uint32_t Ah[4][4], Al[4][4], Bh1[2][4], Bl1[2][4], Bh2[2][4], Bl2[2][4];
#pragma unroll
            for (int mi = 0; mi < 4; mi++) LDSM4(Ah[mi], base + a_off[mi] + kb);
#pragma unroll
            for (int mi = 0; mi < 4; mi++) LDSM4(Al[mi], base + CSZ + a_off[mi] + kb);
#pragma unroll
            for (int ni = 0; ni < 2; ni++) LDSM4(Bh1[ni], base + 2 * CSZ + b_off[ni] + kb);
#pragma unroll
            for (int ni = 0; ni < 2; ni++) LDSM4(Bl1[ni], base + 3 * CSZ + b_off[ni] + kb);
#pragma unroll
            for (int ni = 0; ni < 2; ni++) LDSM4(Bh2[ni], base + 4 * CSZ + b_off[ni] + kb);
#pragma unroll
            for (int ni = 0; ni < 2; ni++) LDSM4(Bl2[ni], base + 5 * CSZ + b_off[ni] + kb);
#pragma unroll
            for (int mi = 0; mi < 4; mi++)
#pragma unroll
                for (int ni = 0; ni < 2; ni++)
#pragma unroll
                    for (int hh = 0; hh < 2; hh++) {
                        int nj = ni * 2 + hh;
                        MMA_BF16(acc1[mi][nj], Ah[mi], Bh1[ni] + hh * 2);
                        MMA_BF16(acc1[mi][nj], Ah[mi], Bl1[ni] + hh * 2);
                        MMA_BF16(acc1[mi][nj], Al[mi], Bh1[ni] + hh * 2);
                        MMA_BF16(acc2[mi][nj], Ah[mi], Bh2[ni] + hh * 2);
                        MMA_BF16(acc2[mi][nj], Ah[mi], Bl2[ni] + hh * 2);
                        MMA_BF16(acc2[mi][nj], Al[mi], Bh2[ni] + hh * 2);
                    }
        }
        __syncthreads();
        if (s < 29) load_stage(s + 3, st);
    }

    // --- SwiGLU epilogue, write h as bf16 hi/lo ---
#pragma unroll
    for (int mi = 0; mi < 4; mi++) {
        int rbase = m0 + wm * 64 + mi * 16 + (lane >> 2);
#pragma unroll
        for (int rr = 0; rr < 2; rr++) {
            int r = rbase + rr * 8;
            if (r < kept) {
                size_t ro = (size_t)(e * CAP + r) * HD;
#pragma unroll
                for (int nj = 0; nj < 4; nj++) {
                    int col = n0 + wn * 32 + nj * 8 + (lane & 3) * 2;
                    float v0 = acc1[mi][nj][rr * 2 + 0], v1 = acc1[mi][nj][rr * 2 + 1];
                    float g0 = acc2[mi][nj][rr * 2 + 0], g1 = acc2[mi][nj][rr * 2 + 1];
                    float h0 = v0 / (1.f + __expf(-v0)) * g0;
                    float h1 = v1 / (1.f + __expf(-v1)) * g1;
                    __nv_bfloat16 h0h = __float2bfloat16(h0);
                    __nv_bfloat16 h1h = __float2bfloat16(h1);
                    __nv_bfloat16 l0h = __float2bfloat16(h0 - __bfloat162float(h0h));
                    __nv_bfloat16 l1h = __float2bfloat16(h1 - __bfloat162float(h1h));
                    *(__nv_bfloat162*)(g_hhi + ro + col) = __halves2bfloat162(h0h, h1h);
                    *(__nv_bfloat162*)(g_hlo + ro + col) = __halves2bfloat162(l0h, l1h);
                }
            }
        }
    }
}

// ============================================================
// 5) GEMM2: out = H . fc2^T, K = 2048
// ============================================================
__global__ __launch_bounds__(256, 1) void gemm2_mma()
{
    extern __shared__ char smem[];
    int e = blockIdx.z;
    int kept = g_kept[e];
    int m0 = blockIdx.x * 128;
    if (m0 >= kept) return;
    int n0 = blockIdx.y * 128;

    uint32_t sb = smem_u32(smem);
    int tid = threadIdx.x, lane = tid & 31, wid = tid >> 5;
    int wm = wid & 1, wn = wid >> 1;

    const __nv_bfloat16* gsrc[8];
    uint32_t sdst[8];
#pragma unroll
    for (int ci = 0; ci < 2; ci++) {
        int c = tid + ci * 256;
        int row = c >> 2, kc = c & 3;
        size_t ar = (size_t)(e * CAP + m0 + row) * HD + kc * 8;
        size_t br = ((size_t)e * IN_D + n0 + row) * HD + kc * 8;
        gsrc[ci * 4 + 0] = g_hhi + ar;
        gsrc[ci * 4 + 1] = g_hlo + ar;
        gsrc[ci * 4 + 2] = g_w2hi + br;
        gsrc[ci * 4 + 3] = g_w2lo + br;
        uint32_t sd = sb + row * LDSROW + kc * 16;
#pragma unroll
        for (int comp = 0; comp < 4; comp++) sdst[ci * 4 + comp] = sd + comp * CSZ;
    }

    const int STG = 4 * CSZ;   // 40960 per stage, 4 stages
    auto load_stage = [&](int slab, int st) {
        int ko = slab * 32;
        uint32_t so = st * STG;
#pragma unroll
        for (int i = 0; i < 8; i++) CPA16(sdst[i] + so, gsrc[i] + ko);
        asm volatile("cp.async.commit_group;" ::: "memory");
    };
    load_stage(0, 0);
    load_stage(1, 1);
    load_stage(2, 2);
    load_stage(3, 3);

    uint32_t a_off[4], b_off[2];
#pragma unroll
    for (int mi = 0; mi < 4; mi++)
        a_off[mi] = (wm * 64 + mi * 16 + (lane & 15)) * LDSROW + (lane >> 4) * 16;
#pragma unroll
    for (int ni = 0; ni < 2; ni++)
        b_off[ni] = (wn * 32 + ni * 16 + (lane & 7) + ((lane >> 4) << 3)) * LDSROW
                    + ((lane >> 3) & 1) * 16;

    float acc[4][4][4];
#pragma unroll
    for (int mi = 0; mi < 4; mi++)
#pragma unroll
        for (int nj = 0; nj < 4; nj++)
#pragma unroll
            for (int q = 0; q < 4; q++) acc[mi][nj][q] = 0.f;

    for (int s = 0; s < 64; s++) {
        int st = s & 3;
        if (s < 60) asm volatile("cp.async.wait_group 3;" ::: "memory");
        else        asm volatile("cp.async.wait_group 0;" ::: "memory");
        __syncthreads();
        uint32_t base = sb + st * STG;
#pragma unroll
        for (int ks = 0; ks < 2; ks++) {
            uint32_t kb = ks * 32;
            uint32_t Ah[4][4], Al[4][4], Bh[2][4], Bl[2][4];
#pragma unroll
            for (int mi = 0; mi < 4; mi++) LDSM4(Ah[mi], base + a_off[mi] + kb);
#pragma unroll
            for (int mi = 0; mi < 4; mi++) LDSM4(Al[mi], base + CSZ + a_off[mi] + kb);
#pragma unroll
            for (int ni = 0; ni < 2; ni++) LDSM4(Bh[ni], base + 2 * CSZ + b_off[ni] + kb);
#pragma unroll
            for (int ni = 0; ni < 2; ni++) LDSM4(Bl[ni], base + 3 * CSZ + b_off[ni] + kb);
#pragma unroll
            for (int mi = 0; mi < 4; mi++)
#pragma unroll
                for (int ni = 0; ni < 2; ni++)
#pragma unroll
                    for (int hh = 0; hh < 2; hh++) {
                        int nj = ni * 2 + hh;
                        MMA_BF16(acc[mi][nj], Ah[mi], Bh[ni] + hh * 2);
                        MMA_BF16(acc[mi][nj], Ah[mi], Bl[ni] + hh * 2);
                        MMA_BF16(acc[mi][nj], Al[mi], Bh[ni] + hh * 2);
                    }
        }
        __syncthreads();
        if (s < 60) load_stage(s + 4, st);
    }

#pragma unroll
    for (int mi = 0; mi < 4; mi++) {
        int rbase = m0 + wm * 64 + mi * 16 + (lane >> 2);
#pragma unroll
        for (int rr = 0; rr < 2; rr++) {
            int r = rbase + rr * 8;
            if (r < kept) {
                size_t ro = (size_t)(e * CAP + r) * IN_D;
#pragma unroll
                for (int nj = 0; nj < 4; nj++) {
                    int col = n0 + wn * 32 + nj * 8 + (lane & 3) * 2;
                    float2 v;
                    v.x = acc[mi][nj][rr * 2 + 0];
                    v.y = acc[mi][nj][rr * 2 + 1];
                    *(float2*)(g_buf_out + ro + col) = v;
                }
            }
        }
    }
}

// ============================================================
// 6) combine
// ============================================================
__global__ __launch_bounds__(256) void combine_kernel(float* __restrict__ out)
{
    int t = blockIdx.x;
    int s1 = g_slot[2 * t];
    int s2 = g_slot[2 * t + 1];
    float w1 = (s1 >= 0) ? g_w[2 * t] : 0.f;
    float w2 = (s2 >= 0) ? g_w[2 * t + 1] : 0.f;
    const float4* r1 = (s1 >= 0) ? (const float4*)(g_buf_out + (size_t)s1 * IN_D) : nullptr;
    const float4* r2 = (s2 >= 0) ? (const float4*)(g_buf_out + (size_t)s2 * IN_D) : nullptr;

    int d = threadIdx.x;
    float4 v = make_float4(0, 0, 0, 0);
    if (r1) {
        float4 a = r1[d];
        v.x += w1 * a.x; v.y += w1 * a.y; v.z += w1 * a.z; v.w += w1 * a.w;
    }
    if (r2) {
        float4 a = r2[d];
        v.x += w2 * a.x; v.y += w2 * a.y; v.z += w2 * a.z; v.w += w2 * a.w;
    }
    ((float4*)(out + (size_t)t * IN_D))[d] = v;
}

// ============================================================
extern "C" void kernel_launch(void* const* d_in, const int* in_sizes, int n_in,
                              void* d_out, int out_size)
{
    const float* x      = (const float*)d_in[0];
    const float* gate_w = (const float*)d_in[1];
    const float* fc1_w  = (const float*)d_in[2];
    const float* gating = (const float*)d_in[3];
    const float* fc2_w  = (const float*)d_in[4];
    float* out = (float*)d_out;
    float* loss_ptr = (out_size > NTOK * IN_D) ? out + (size_t)NTOK * IN_D : nullptr;

    const int smem1 = 3 * 6 * CSZ;   // 184320
    const int smem2 = 4 * 4 * CSZ;   // 163840
    cudaFuncSetAttribute(gemm1_mma, cudaFuncAttributeMaxDynamicSharedMemorySize, smem1);
    cudaFuncSetAttribute(gemm2_mma, cudaFuncAttributeMaxDynamicSharedMemorySize, smem2);

    const int n4 = NTOK * IN_D / 4;   // 4194304, same count for all 4 arrays
    split_kernel<<<2048, 256>>>((const float4*)x,      0, n4);
    split_kernel<<<2048, 256>>>((const float4*)fc1_w,  1, n4);
    split_kernel<<<2048, 256>>>((const float4*)gating, 2, n4);
    split_kernel<<<2048, 256>>>((const float4*)fc2_w,  3, n4);

    route_kernel<<<ROUTE_BLOCKS, 256>>>(x, gate_w);
    dispatch_kernel<<<1, 1024>>>();
    loss_kernel<<<1, 32>>>(loss_ptr);
    gemm1_mma<<<dim3(CAP / 128, HD / 128, E_NUM), 256, smem1>>>();
    gemm2_mma<<<dim3(CAP / 128, IN_D / 128, E_NUM), 256, smem2>>>();
    combine_kernel<<<NTOK, 256>>>(out);
}

// round 7
// speedup vs baseline: 3.1252x; 1.3547x over previous
#include <cuda_runtime.h>
#include <cuda_bf16.h>
#include <cuda_fp16.h>
#include <cstdint>
#include <math.h>

// ---------------- problem constants ----------------
#define E_NUM      8
#define TOPK       2
#define IN_D       1024
#define HD         2048
#define NTOK       16384
#define NK         32768
#define CAP        5120
#define ROUTE_BLOCKS 2048

// ---------------- device scratch ----------------
__device__ __half g_xh[(size_t)NTOK * IN_D];
__device__ __half g_xl[(size_t)NTOK * IN_D];
__device__ __half g_w1h[(size_t)E_NUM * HD * IN_D];
__device__ __half g_wgh[(size_t)E_NUM * HD * IN_D];
__device__ __half g_w2h[(size_t)E_NUM * IN_D * HD];
__device__ __half g_hh[(size_t)E_NUM * CAP * HD];
__device__ __half g_hl[(size_t)E_NUM * CAP * HD];
__device__ float g_buf_out[(size_t)E_NUM * CAP * IN_D];
__device__ int   g_exp[NK];
__device__ float g_w[NK];
__device__ int   g_slot[NK];
__device__ int   g_slot_token[E_NUM * CAP];
__device__ int   g_counts[E_NUM];
__device__ int   g_kept[E_NUM];
__device__ float g_prob_part[ROUTE_BLOCKS * E_NUM];

// ---------------- PTX helpers ----------------
__device__ __forceinline__ uint32_t smem_u32(const void* p) {
    uint32_t a;
    asm("{ .reg .u64 t; cvta.to.shared.u64 t, %1; cvt.u32.u64 %0, t; }" : "=r"(a) : "l"(p));
    return a;
}

#define CPA16(dst, src) \
    asm volatile("cp.async.cg.shared.global [%0], [%1], 16;" :: "r"(dst), "l"(src) : "memory")

#define LDSM4(r, addr) \
    asm volatile("ldmatrix.sync.aligned.m8n8.x4.shared.b16 {%0,%1,%2,%3}, [%4];" \
        : "=r"((r)[0]), "=r"((r)[1]), "=r"((r)[2]), "=r"((r)[3]) : "r"(addr))

#define MMA_F16(d, a, bb) \
    asm volatile("mma.sync.aligned.m16n8k16.row.col.f32.f16.f16.f32 " \
        "{%0,%1,%2,%3}, {%4,%5,%6,%7}, {%8,%9}, {%0,%1,%2,%3};" \
        : "+f"((d)[0]), "+f"((d)[1]), "+f"((d)[2]), "+f"((d)[3]) \
        : "r"((a)[0]), "r"((a)[1]), "r"((a)[2]), "r"((a)[3]), \
          "r"((bb)[0]), "r"((bb)[1]))

// ============================================================
// 0a) x: fp32 -> (fp16 hi, fp16 lo)
// ============================================================
__global__ __launch_bounds__(256) void split_x_kernel(const float4* __restrict__ in, int n4)
{
    uint2* hi4 = (uint2*)g_xh;
    uint2* lo4 = (uint2*)g_xl;
    for (int i = blockIdx.x * blockDim.x + threadIdx.x; i < n4;
         i += gridDim.x * blockDim.x) {
        float4 v = in[i];
        __half hx = __float2half_rn(v.x), hy = __float2half_rn(v.y);
        __half hz = __float2half_rn(v.z), hw = __float2half_rn(v.w);
        __half lx = __float2half_rn(v.x - __half2float(hx));
        __half ly = __float2half_rn(v.y - __half2float(hy));
        __half lz = __float2half_rn(v.z - __half2float(hz));
        __half lw = __float2half_rn(v.w - __half2float(hw));
        __half2 h01 = __halves2half2(hx, hy), h23 = __halves2half2(hz, hw);
        __half2 l01 = __halves2half2(lx, ly), l23 = __halves2half2(lz, lw);
        uint2 ho, lo2;
        ho.x = *reinterpret_cast<uint32_t*>(&h01);
        ho.y = *reinterpret_cast<uint32_t*>(&h23);
        lo2.x = *reinterpret_cast<uint32_t*>(&l01);
        lo2.y = *reinterpret_cast<uint32_t*>(&l23);
        hi4[i] = ho;
        lo4[i] = lo2;
    }
}

// ============================================================
// 0b) weights: fp32 -> fp16 (round only)
// ============================================================
__global__ __launch_bounds__(256) void conv_w_kernel(const float4* __restrict__ in,
                                                     int which, int n4)
{
    __half* dst;
    switch (which) {
        case 1: dst = g_w1h; break;
        case 2: dst = g_wgh; break;
        default: dst = g_w2h; break;
    }
    uint2* d4 = (uint2*)dst;
    for (int i = blockIdx.x * blockDim.x + threadIdx.x; i < n4;
         i += gridDim.x * blockDim.x) {
        float4 v = in[i];
        __half2 h01 = __halves2half2(__float2half_rn(v.x), __float2half_rn(v.y));
        __half2 h23 = __halves2half2(__float2half_rn(v.z), __float2half_rn(v.w));
        uint2 o;
        o.x = *reinterpret_cast<uint32_t*>(&h01);
        o.y = *reinterpret_cast<uint32_t*>(&h23);
        d4[i] = o;
    }
}

// ============================================================
// 1) routing
// ============================================================
__global__ __launch_bounds__(256) void route_kernel(const float* __restrict__ x,
                                                    const float* __restrict__ gate_w)
{
    __shared__ float sg[E_NUM * IN_D];
    __shared__ float pp[8][E_NUM];
    for (int i = threadIdx.x; i < E_NUM * IN_D; i += blockDim.x) sg[i] = gate_w[i];
    __syncthreads();

    int w = threadIdx.x >> 5, lane = threadIdx.x & 31;
    int t = blockIdx.x * 8 + w;
    const float* xr = x + (size_t)t * IN_D;
    float acc[E_NUM];
#pragma unroll
    for (int e = 0; e < E_NUM; e++) acc[e] = 0.f;
    for (int j = 0; j < IN_D / 32; j++) {
        float xv = xr[lane + j * 32];
#pragma unroll
        for (int e = 0; e < E_NUM; e++) acc[e] += xv * sg[e * IN_D + lane + j * 32];
    }
#pragma unroll
    for (int off = 16; off > 0; off >>= 1)
#pragma unroll
        for (int e = 0; e < E_NUM; e++) acc[e] += __shfl_down_sync(0xffffffffu, acc[e], off);

    if (lane == 0) {
        float m = acc[0];
#pragma unroll
        for (int e = 1; e < E_NUM; e++) m = fmaxf(m, acc[e]);
        float p[E_NUM], s = 0.f;
#pragma unroll
        for (int e = 0; e < E_NUM; e++) { p[e] = expf(acc[e] - m); s += p[e]; }
        float inv = 1.f / s;
#pragma unroll
        for (int e = 0; e < E_NUM; e++) p[e] *= inv;
        int e1 = 0;
#pragma unroll
        for (int e = 1; e < E_NUM; e++) if (p[e] > p[e1]) e1 = e;
        int e2 = (e1 == 0) ? 1 : 0;
#pragma unroll
        for (int e = 0; e < E_NUM; e++) if (e != e1 && p[e] > p[e2]) e2 = e;
        float denom = p[e1] + p[e2] + 1e-9f;
        g_exp[2 * t] = e1; g_exp[2 * t + 1] = e2;
        g_w[2 * t] = p[e1] / denom; g_w[2 * t + 1] = p[e2] / denom;
#pragma unroll
        for (int e = 0; e < E_NUM; e++) pp[w][e] = p[e];
    }
    __syncthreads();
    if (threadIdx.x < E_NUM) {
        float s = 0.f;
        for (int ww = 0; ww < 8; ww++) s += pp[ww][threadIdx.x];
        g_prob_part[blockIdx.x * E_NUM + threadIdx.x] = s;
    }
}

// ============================================================
// 2) dispatch
// ============================================================
__global__ __launch_bounds__(1024) void dispatch_kernel()
{
    __shared__ int sc[1024 * E_NUM];
    int tid = threadIdx.x, base = tid * 32;
    int h[E_NUM];
#pragma unroll
    for (int e = 0; e < E_NUM; e++) h[e] = 0;
    for (int i = 0; i < 32; i++) h[g_exp[base + i]]++;
#pragma unroll
    for (int e = 0; e < E_NUM; e++) sc[tid * E_NUM + e] = h[e];
    __syncthreads();
    for (int off = 1; off < 1024; off <<= 1) {
        int v[E_NUM];
        if (tid >= off)
#pragma unroll
            for (int e = 0; e < E_NUM; e++) v[e] = sc[(tid - off) * E_NUM + e];
        __syncthreads();
        if (tid >= off)
#pragma unroll
            for (int e = 0; e < E_NUM; e++) sc[tid * E_NUM + e] += v[e];
        __syncthreads();
    }
    int basec[E_NUM];
#pragma unroll
    for (int e = 0; e < E_NUM; e++) basec[e] = sc[tid * E_NUM + e] - h[e];
    if (tid == 1023)
#pragma unroll
        for (int e = 0; e < E_NUM; e++) {
            int c = sc[tid * E_NUM + e];
            g_counts[e] = c;
            g_kept[e] = (c < CAP) ? c : CAP;
        }
    for (int i = 0; i < 32; i++) {
        int idx = base + i;
        int e = g_exp[idx];
        int pos = basec[e]++;
        if (pos < CAP) {
            int s = e * CAP + pos;
            g_slot[idx] = s;
            g_slot_token[s] = idx >> 1;
        } else g_slot[idx] = -1;
    }
}

// ============================================================
// 3) loss
// ============================================================
__global__ void loss_kernel(float* out_loss)
{
    __shared__ float ps[E_NUM];
    if (threadIdx.x < E_NUM) {
        float s = 0.f;
        for (int b = 0; b < ROUTE_BLOCKS; b++) s += g_prob_part[b * E_NUM + threadIdx.x];
        float p = s / (float)NTOK;
        float f = (float)g_counts[threadIdx.x] / (float)NK;
        ps[threadIdx.x] = p * f;
    }
    __syncthreads();
    if (threadIdx.x == 0 && out_loss) {
        float s = 0.f;
#pragma unroll
        for (int e = 0; e < E_NUM; e++) s += ps[e];
        *out_loss = (float)E_NUM * s;
    }
}

// ============================================================
// GEMM tiling: 128x128 tile, BK=32, 8 warps (64x32 warp tile)
// smem rows padded to 80B (conflict-free ldmatrix)
// fp16x2 split: acc += A_hi*B + A_lo*B  (B rounded to fp16)
// ============================================================
#define LDSROW 80
#define CSZ    (128 * LDSROW)   // 10240 B per component tile

// ============================================================
// 4) GEMM1: h = silu(Xg . fc1^T) * (Xg . gating^T), K = 1024
//    comps per stage: [xh, xl, w1, wg]  -> 4 stages
// ============================================================
__global__ __launch_bounds__(256, 1) void gemm1_mma()
{
    extern __shared__ char smem[];
    int e = blockIdx.z;
    int kept = g_kept[e];
    int m0 = blockIdx.x * 128;
    if (m0 >= kept) return;
    int n0 = blockIdx.y * 128;

    uint32_t sb = smem_u32(smem);
    int tid = threadIdx.x, lane = tid & 31, wid = tid >> 5;
    int wm = wid & 1, wn = wid >> 1;

    const __half* gsrc[8];
    uint32_t sdst[8];
#pragma unroll
    for (int ci = 0; ci < 2; ci++) {
        int c = tid + ci * 256;
        int row = c >> 2, kc = c & 3;
        int tok = g_slot_token[e * CAP + m0 + row] & (NTOK - 1);
        size_t ar = (size_t)tok * IN_D + kc * 8;
        size_t br = ((size_t)e * HD + n0 + row) * IN_D + kc * 8;
        gsrc[ci * 4 + 0] = g_xh + ar;
        gsrc[ci * 4 + 1] = g_xl + ar;
        gsrc[ci * 4 + 2] = g_w1h + br;
        gsrc[ci * 4 + 3] = g_wgh + br;
        uint32_t sd = sb + row * LDSROW + kc * 16;
#pragma unroll
        for (int comp = 0; comp < 4; comp++) sdst[ci * 4 + comp] = sd + comp * CSZ;
    }

    const int STG = 4 * CSZ;   // 40960 per stage, 4 stages
    auto load_stage = [&](int slab, int st) {
        int ko = slab * 32;
        uint32_t so = st * STG;
#pragma unroll
        for (int i = 0; i < 8; i++) CPA16(sdst[i] + so, gsrc[i] + ko);
        asm volatile("cp.async.commit_group;" ::: "memory");
    };
    load_stage(0, 0);
    load_stage(1, 1);
    load_stage(2, 2);
    load_stage(3, 3);

    uint32_t a_off[4], b_off[2];
#pragma unroll
    for (int mi = 0; mi < 4; mi++)
        a_off[mi] = (wm * 64 + mi * 16 + (lane & 15)) * LDSROW + (lane >> 4) * 16;
#pragma unroll
    for (int ni = 0; ni < 2; ni++)
        b_off[ni] = (wn * 32 + ni * 16 + (lane & 7) + ((lane >> 4) << 3)) * LDSROW
                    + ((lane >> 3) & 1) * 16;

    float acc1[4][4][4], acc2[4][4][4];
#pragma unroll
    for (int mi = 0; mi < 4; mi++)
#pragma unroll
        for (int nj = 0; nj < 4; nj++)
#pragma unroll
            for (int q = 0; q < 4; q++) { acc1[mi][nj][q] = 0.f; acc2[mi][nj][q] = 0.f; }

    for (int s = 0; s < 32; s++) {
        int st = s & 3;
        if (s < 28) asm volatile("cp.async.wait_group 3;" ::: "memory");
        else        asm volatile("cp.async.wait_group 0;" ::: "memory");
        __syncthreads();
        uint32_t base = sb + st * STG;
#pragma unroll
        for (int ks = 0; ks < 2; ks++) {
            uint32_t kb = ks * 32;
            uint32_t Ah[4][4], Al[4][4], B1[2][4], B2[2][4];
#pragma unroll
            for (int mi = 0; mi < 4; mi++) LDSM4(Ah[mi], base + a_off[mi] + kb);
#pragma unroll
            for (int mi = 0; mi < 4; mi++) LDSM4(Al[mi], base + CSZ + a_off[mi] + kb);
#pragma unroll
            for (int ni = 0; ni < 2; ni++) LDSM4(B1[ni], base + 2 * CSZ + b_off[ni] + kb);
#pragma unroll
            for (int ni = 0; ni < 2; ni++) LDSM4(B2[ni], base + 3 * CSZ + b_off[ni] + kb);
#pragma unroll
            for (int mi = 0; mi < 4; mi++)
#pragma unroll
                for (int ni = 0; ni < 2; ni++)
#pragma unroll
                    for (int hh = 0; hh < 2; hh++) {
                        int nj = ni * 2 + hh;
                        MMA_F16(acc1[mi][nj], Ah[mi], B1[ni] + hh * 2);
                        MMA_F16(acc1[mi][nj], Al[mi], B1[ni] + hh * 2);
                        MMA_F16(acc2[mi][nj], Ah[mi], B2[ni] + hh * 2);
                        MMA_F16(acc2[mi][nj], Al[mi], B2[ni] + hh * 2);
                    }
        }
        __syncthreads();
        if (s < 28) load_stage(s + 4, st);
    }

    // --- SwiGLU epilogue, write h as fp16 hi/lo ---
#pragma unroll
    for (int mi = 0; mi < 4; mi++) {
        int rbase = m0 + wm * 64 + mi * 16 + (lane >> 2);
#pragma unroll
        for (int rr = 0; rr < 2; rr++) {
            int r = rbase + rr * 8;
            if (r < kept) {
                size_t ro = (size_t)(e * CAP + r) * HD;
#pragma unroll
                for (int nj = 0; nj < 4; nj++) {
                    int col = n0 + wn * 32 + nj * 8 + (lane & 3) * 2;
                    float v0 = acc1[mi][nj][rr * 2 + 0], v1 = acc1[mi][nj][rr * 2 + 1];
                    float g0 = acc2[mi][nj][rr * 2 + 0], g1 = acc2[mi][nj][rr * 2 + 1];
                    float h0 = v0 / (1.f + __expf(-v0)) * g0;
                    float h1 = v1 / (1.f + __expf(-v1)) * g1;
                    __half h0h = __float2half_rn(h0);
                    __half h1h = __float2half_rn(h1);
                    __half l0h = __float2half_rn(h0 - __half2float(h0h));
                    __half l1h = __float2half_rn(h1 - __half2float(h1h));
                    *(__half2*)(g_hh + ro + col) = __halves2half2(h0h, h1h);
                    *(__half2*)(g_hl + ro + col) = __halves2half2(l0h, l1h);
                }
            }
        }
    }
}

// ============================================================
// 5) GEMM2: out = H . fc2^T, K = 2048
//    comps per stage: [hh, hl, w2]  -> 4 stages
// ============================================================
__global__ __launch_bounds__(256, 1) void gemm2_mma()
{
    extern __shared__ char smem[];
    int e = blockIdx.z;
    int kept = g_kept[e];
    int m0 = blockIdx.x * 128;
    if (m0 >= kept) return;
    int n0 = blockIdx.y * 128;

    uint32_t sb = smem_u32(smem);
    int tid = threadIdx.x, lane = tid & 31, wid = tid >> 5;
    int wm = wid & 1, wn = wid >> 1;

    const __half* gsrc[6];
    uint32_t sdst[6];
#pragma unroll
    for (int ci = 0; ci < 2; ci++) {
        int c = tid + ci * 256;
        int row = c >> 2, kc = c & 3;
        size_t ar = (size_t)(e * CAP + m0 + row) * HD + kc * 8;
        size_t br = ((size_t)e * IN_D + n0 + row) * HD + kc * 8;
        gsrc[ci * 3 + 0] = g_hh + ar;
        gsrc[ci * 3 + 1] = g_hl + ar;
        gsrc[ci * 3 + 2] = g_w2h + br;
        uint32_t sd = sb + row * LDSROW + kc * 16;
#pragma unroll
        for (int comp = 0; comp < 3; comp++) sdst[ci * 3 + comp] = sd + comp * CSZ;
    }

    const int STG = 3 * CSZ;   // 30720 per stage, 4 stages
    auto load_stage = [&](int slab, int st) {
        int ko = slab * 32;
        uint32_t so = st * STG;
#pragma unroll
        for (int i = 0; i < 6; i++) CPA16(sdst[i] + so, gsrc[i] + ko);
        asm volatile("cp.async.commit_group;" ::: "memory");
    };
    load_stage(0, 0);
    load_stage(1, 1);
    load_stage(2, 2);
    load_stage(3, 3);

    uint32_t a_off[4], b_off[2];
#pragma unroll
    for (int mi = 0; mi < 4; mi++)
        a_off[mi] = (wm * 64 + mi * 16 + (lane & 15)) * LDSROW + (lane >> 4) * 16;
#pragma unroll
    for (int ni = 0; ni < 2; ni++)
        b_off[ni] = (wn * 32 + ni * 16 + (lane & 7) + ((lane >> 4) << 3)) * LDSROW
                    + ((lane >> 3) & 1) * 16;

    float acc[4][4][4];
#pragma unroll
    for (int mi = 0; mi < 4; mi++)
#pragma unroll
        for (int nj = 0; nj < 4; nj++)
#pragma unroll
            for (int q = 0; q < 4; q++) acc[mi][nj][q] = 0.f;

    for (int s = 0; s < 64; s++) {
        int st = s & 3;
        if (s < 60) asm volatile("cp.async.wait_group 3;" ::: "memory");
        else        asm volatile("cp.async.wait_group 0;" ::: "memory");
        __syncthreads();
        uint32_t base = sb + st * STG;
#pragma unroll
        for (int ks = 0; ks < 2; ks++) {
            uint32_t kb = ks * 32;
            uint32_t Ah[4][4], Al[4][4], B[2][4];
#pragma unroll
            for (int mi = 0; mi < 4; mi++) LDSM4(Ah[mi], base + a_off[mi] + kb);
#pragma unroll
            for (int mi = 0; mi < 4; mi++) LDSM4(Al[mi], base + CSZ + a_off[mi] + kb);
#pragma unroll
            for (int ni = 0; ni < 2; ni++) LDSM4(B[ni], base + 2 * CSZ + b_off[ni] + kb);
#pragma unroll
            for (int mi = 0; mi < 4; mi++)
#pragma unroll
                for (int ni = 0; ni < 2; ni++)
#pragma unroll
                    for (int hh = 0; hh < 2; hh++) {
                        int nj = ni * 2 + hh;
                        MMA_F16(acc[mi][nj], Ah[mi], B[ni] + hh * 2);
                        MMA_F16(acc[mi][nj], Al[mi], B[ni] + hh * 2);
                    }
        }
        __syncthreads();
        if (s < 60) load_stage(s + 4, st);
    }

#pragma unroll
    for (int mi = 0; mi < 4; mi++) {
        int rbase = m0 + wm * 64 + mi * 16 + (lane >> 2);
#pragma unroll
        for (int rr = 0; rr < 2; rr++) {
            int r = rbase + rr * 8;
            if (r < kept) {
                size_t ro = (size_t)(e * CAP + r) * IN_D;
#pragma unroll
                for (int nj = 0; nj < 4; nj++) {
                    int col = n0 + wn * 32 + nj * 8 + (lane & 3) * 2;
                    float2 v;
                    v.x = acc[mi][nj][rr * 2 + 0];
                    v.y = acc[mi][nj][rr * 2 + 1];
                    *(float2*)(g_buf_out + ro + col) = v;
                }
            }
        }
    }
}

// ============================================================
// 6) combine
// ============================================================
__global__ __launch_bounds__(256) void combine_kernel(float* __restrict__ out)
{
    int t = blockIdx.x;
    int s1 = g_slot[2 * t];
    int s2 = g_slot[2 * t + 1];
    float w1 = (s1 >= 0) ? g_w[2 * t] : 0.f;
    float w2 = (s2 >= 0) ? g_w[2 * t + 1] : 0.f;
    const float4* r1 = (s1 >= 0) ? (const float4*)(g_buf_out + (size_t)s1 * IN_D) : nullptr;
    const float4* r2 = (s2 >= 0) ? (const float4*)(g_buf_out + (size_t)s2 * IN_D) : nullptr;

    int d = threadIdx.x;
    float4 v = make_float4(0, 0, 0, 0);
    if (r1) {
        float4 a = r1[d];
        v.x += w1 * a.x; v.y += w1 * a.y; v.z += w1 * a.z; v.w += w1 * a.w;
    }
    if (r2) {
        float4 a = r2[d];
        v.x += w2 * a.x; v.y += w2 * a.y; v.z += w2 * a.z; v.w += w2 * a.w;
    }
    ((float4*)(out + (size_t)t * IN_D))[d] = v;
}

// ============================================================
extern "C" void kernel_launch(void* const* d_in, const int* in_sizes, int n_in,
                              void* d_out, int out_size)
{
    const float* x      = (const float*)d_in[0];
    const float* gate_w = (const float*)d_in[1];
    const float* fc1_w  = (const float*)d_in[2];
    const float* gating = (const float*)d_in[3];
    const float* fc2_w  = (const float*)d_in[4];
    float* out = (float*)d_out;
    float* loss_ptr = (out_size > NTOK * IN_D) ? out + (size_t)NTOK * IN_D : nullptr;

    const int smem1 = 4 * 4 * CSZ;   // 163840
    const int smem2 = 4 * 3 * CSZ;   // 122880
    cudaFuncSetAttribute(gemm1_mma, cudaFuncAttributeMaxDynamicSharedMemorySize, smem1);
    cudaFuncSetAttribute(gemm2_mma, cudaFuncAttributeMaxDynamicSharedMemorySize, smem2);

    const int n4 = NTOK * IN_D / 4;   // 4194304 float4s for each tensor
    split_x_kernel<<<2048, 256>>>((const float4*)x, n4);
    conv_w_kernel<<<2048, 256>>>((const float4*)fc1_w,  1, n4);
    conv_w_kernel<<<2048, 256>>>((const float4*)gating, 2, n4);
    conv_w_kernel<<<2048, 256>>>((const float4*)fc2_w,  3, n4);

    route_kernel<<<ROUTE_BLOCKS, 256>>>(x, gate_w);
    dispatch_kernel<<<1, 1024>>>();
    loss_kernel<<<1, 32>>>(loss_ptr);
    gemm1_mma<<<dim3(CAP / 128, HD / 128, E_NUM), 256, smem1>>>();
    gemm2_mma<<<dim3(CAP / 128, IN_D / 128, E_NUM), 256, smem2>>>();
    combine_kernel<<<NTOK, 256>>>(out);
}

// round 8
// speedup vs baseline: 3.8341x; 1.2268x over previous
#include <cuda_runtime.h>
#include <cuda_bf16.h>
#include <cuda_fp16.h>
#include <cstdint>
#include <math.h>

// ---------------- problem constants ----------------
#define E_NUM      8
#define TOPK       2
#define IN_D       1024
#define HD         2048
#define NTOK       16384
#define NK         32768
#define CAP        5120
#define ROUTE_BLOCKS 2048

// ---------------- device scratch ----------------
__device__ __half g_xh[(size_t)NTOK * IN_D];
__device__ __half g_xl[(size_t)NTOK * IN_D];
__device__ __half g_w1h[(size_t)E_NUM * HD * IN_D];
__device__ __half g_wgh[(size_t)E_NUM * HD * IN_D];
__device__ __half g_w2h[(size_t)E_NUM * IN_D * HD];
__device__ __half g_hh[(size_t)E_NUM * CAP * HD];
__device__ float g_buf_out[(size_t)E_NUM * CAP * IN_D];
__device__ int   g_exp[NK];
__device__ float g_w[NK];
__device__ int   g_slot[NK];
__device__ int   g_slot_token[E_NUM * CAP];
__device__ int   g_counts[E_NUM];
__device__ int   g_kept[E_NUM];
__device__ float g_prob_part[ROUTE_BLOCKS * E_NUM];

// ---------------- PTX helpers ----------------
__device__ __forceinline__ uint32_t smem_u32(const void* p) {
    uint32_t a;
    asm("{ .reg .u64 t; cvta.to.shared.u64 t, %1; cvt.u32.u64 %0, t; }" : "=r"(a) : "l"(p));
    return a;
}

#define CPA16(dst, src) \
    asm volatile("cp.async.cg.shared.global [%0], [%1], 16;" :: "r"(dst), "l"(src) : "memory")

#define LDSM4(r, addr) \
    asm volatile("ldmatrix.sync.aligned.m8n8.x4.shared.b16 {%0,%1,%2,%3}, [%4];" \
        : "=r"((r)[0]), "=r"((r)[1]), "=r"((r)[2]), "=r"((r)[3]) : "r"(addr))

#define MMA_F16(d, a, bb) \
    asm volatile("mma.sync.aligned.m16n8k16.row.col.f32.f16.f16.f32 " \
        "{%0,%1,%2,%3}, {%4,%5,%6,%7}, {%8,%9}, {%0,%1,%2,%3};" \
        : "+f"((d)[0]), "+f"((d)[1]), "+f"((d)[2]), "+f"((d)[3]) \
        : "r"((a)[0]), "r"((a)[1]), "r"((a)[2]), "r"((a)[3]), \
          "r"((bb)[0]), "r"((bb)[1]))

// ============================================================
// 0a) x: fp32 -> (fp16 hi, fp16 lo)
// ============================================================
__global__ __launch_bounds__(256) void split_x_kernel(const float4* __restrict__ in, int n4)
{
    uint2* hi4 = (uint2*)g_xh;
    uint2* lo4 = (uint2*)g_xl;
    for (int i = blockIdx.x * blockDim.x + threadIdx.x; i < n4;
         i += gridDim.x * blockDim.x) {
        float4 v = in[i];
        __half hx = __float2half_rn(v.x), hy = __float2half_rn(v.y);
        __half hz = __float2half_rn(v.z), hw = __float2half_rn(v.w);
        __half lx = __float2half_rn(v.x - __half2float(hx));
        __half ly = __float2half_rn(v.y - __half2float(hy));
        __half lz = __float2half_rn(v.z - __half2float(hz));
        __half lw = __float2half_rn(v.w - __half2float(hw));
        __half2 h01 = __halves2half2(hx, hy), h23 = __halves2half2(hz, hw);
        __half2 l01 = __halves2half2(lx, ly), l23 = __halves2half2(lz, lw);
        uint2 ho, lo2;
        ho.x = *reinterpret_cast<uint32_t*>(&h01);
        ho.y = *reinterpret_cast<uint32_t*>(&h23);
        lo2.x = *reinterpret_cast<uint32_t*>(&l01);
        lo2.y = *reinterpret_cast<uint32_t*>(&l23);
        hi4[i] = ho;
        lo4[i] = lo2;
    }
}

// ============================================================
// 0b) weights: fp32 -> fp16 (round only)
// ============================================================
__global__ __launch_bounds__(256) void conv_w_kernel(const float4* __restrict__ in,
                                                     int which, int n4)
{
    __half* dst;
    switch (which) {
        case 1: dst = g_w1h; break;
        case 2: dst = g_wgh; break;
        default: dst = g_w2h; break;
    }
    uint2* d4 = (uint2*)dst;
    for (int i = blockIdx.x * blockDim.x + threadIdx.x; i < n4;
         i += gridDim.x * blockDim.x) {
        float4 v = in[i];
        __half2 h01 = __halves2half2(__float2half_rn(v.x), __float2half_rn(v.y));
        __half2 h23 = __halves2half2(__float2half_rn(v.z), __float2half_rn(v.w));
        uint2 o;
        o.x = *reinterpret_cast<uint32_t*>(&h01);
        o.y = *reinterpret_cast<uint32_t*>(&h23);
        d4[i] = o;
    }
}

// ============================================================
// 1) routing
// ============================================================
__global__ __launch_bounds__(256) void route_kernel(const float* __restrict__ x,
                                                    const float* __restrict__ gate_w)
{
    __shared__ float sg[E_NUM * IN_D];
    __shared__ float pp[8][E_NUM];
    for (int i = threadIdx.x; i < E_NUM * IN_D; i += blockDim.x) sg[i] = gate_w[i];
    __syncthreads();

    int w = threadIdx.x >> 5, lane = threadIdx.x & 31;
    int t = blockIdx.x * 8 + w;
    const float* xr = x + (size_t)t * IN_D;
    float acc[E_NUM];
#pragma unroll
    for (int e = 0; e < E_NUM; e++) acc[e] = 0.f;
    for (int j = 0; j < IN_D / 32; j++) {
        float xv = xr[lane + j * 32];
#pragma unroll
        for (int e = 0; e < E_NUM; e++) acc[e] += xv * sg[e * IN_D + lane + j * 32];
    }
#pragma unroll
    for (int off = 16; off > 0; off >>= 1)
#pragma unroll
        for (int e = 0; e < E_NUM; e++) acc[e] += __shfl_down_sync(0xffffffffu, acc[e], off);

    if (lane == 0) {
        float m = acc[0];
#pragma unroll
        for (int e = 1; e < E_NUM; e++) m = fmaxf(m, acc[e]);
        float p[E_NUM], s = 0.f;
#pragma unroll
        for (int e = 0; e < E_NUM; e++) { p[e] = expf(acc[e] - m); s += p[e]; }
        float inv = 1.f / s;
#pragma unroll
        for (int e = 0; e < E_NUM; e++) p[e] *= inv;
        int e1 = 0;
#pragma unroll
        for (int e = 1; e < E_NUM; e++) if (p[e] > p[e1]) e1 = e;
        int e2 = (e1 == 0) ? 1 : 0;
#pragma unroll
        for (int e = 0; e < E_NUM; e++) if (e != e1 && p[e] > p[e2]) e2 = e;
        float denom = p[e1] + p[e2] + 1e-9f;
        g_exp[2 * t] = e1; g_exp[2 * t + 1] = e2;
        g_w[2 * t] = p[e1] / denom; g_w[2 * t + 1] = p[e2] / denom;
#pragma unroll
        for (int e = 0; e < E_NUM; e++) pp[w][e] = p[e];
    }
    __syncthreads();
    if (threadIdx.x < E_NUM) {
        float s = 0.f;
        for (int ww = 0; ww < 8; ww++) s += pp[ww][threadIdx.x];
        g_prob_part[blockIdx.x * E_NUM + threadIdx.x] = s;
    }
}

// ============================================================
// 2) dispatch
// ============================================================
__global__ __launch_bounds__(1024) void dispatch_kernel()
{
    __shared__ int sc[1024 * E_NUM];
    int tid = threadIdx.x, base = tid * 32;
    int h[E_NUM];
#pragma unroll
    for (int e = 0; e < E_NUM; e++) h[e] = 0;
    for (int i = 0; i < 32; i++) h[g_exp[base + i]]++;
#pragma unroll
    for (int e = 0; e < E_NUM; e++) sc[tid * E_NUM + e] = h[e];
    __syncthreads();
    for (int off = 1; off < 1024; off <<= 1) {
        int v[E_NUM];
        if (tid >= off)
#pragma unroll
            for (int e = 0; e < E_NUM; e++) v[e] = sc[(tid - off) * E_NUM + e];
        __syncthreads();
        if (tid >= off)
#pragma unroll
            for (int e = 0; e < E_NUM; e++) sc[tid * E_NUM + e] += v[e];
        __syncthreads();
    }
    int basec[E_NUM];
#pragma unroll
    for (int e = 0; e < E_NUM; e++) basec[e] = sc[tid * E_NUM + e] - h[e];
    if (tid == 1023)
#pragma unroll
        for (int e = 0; e < E_NUM; e++) {
            int c = sc[tid * E_NUM + e];
            g_counts[e] = c;
            g_kept[e] = (c < CAP) ? c : CAP;
        }
    for (int i = 0; i < 32; i++) {
        int idx = base + i;
        int e = g_exp[idx];
        int pos = basec[e]++;
        if (pos < CAP) {
            int s = e * CAP + pos;
            g_slot[idx] = s;
            g_slot_token[s] = idx >> 1;
        } else g_slot[idx] = -1;
    }
}

// ============================================================
// 3) loss
// ============================================================
__global__ void loss_kernel(float* out_loss)
{
    __shared__ float ps[E_NUM];
    if (threadIdx.x < E_NUM) {
        float s = 0.f;
        for (int b = 0; b < ROUTE_BLOCKS; b++) s += g_prob_part[b * E_NUM + threadIdx.x];
        float p = s / (float)NTOK;
        float f = (float)g_counts[threadIdx.x] / (float)NK;
        ps[threadIdx.x] = p * f;
    }
    __syncthreads();
    if (threadIdx.x == 0 && out_loss) {
        float s = 0.f;
#pragma unroll
        for (int e = 0; e < E_NUM; e++) s += ps[e];
        *out_loss = (float)E_NUM * s;
    }
}

// ============================================================
// GEMM tiling: 128x128 tile, BK=32, 8 warps (64x32 warp tile)
// smem rows padded to 80B (conflict-free ldmatrix)
// Single-barrier pipeline: depth-3 prefetch over 4 slots
// ============================================================
#define LDSROW 80
#define CSZ    (128 * LDSROW)   // 10240 B per component tile

// ============================================================
// 4) GEMM1: h = silu(Xg . fc1^T) * (Xg . gating^T), K = 1024
//    comps per stage: [xh, xl, w1, wg]; acc += (A_hi + A_lo) * B_fp16
// ============================================================
__global__ __launch_bounds__(256, 1) void gemm1_mma()
{
    extern __shared__ char smem[];
    int e = blockIdx.z;
    int kept = g_kept[e];
    int m0 = blockIdx.x * 128;
    if (m0 >= kept) return;
    int n0 = blockIdx.y * 128;

    uint32_t sb = smem_u32(smem);
    int tid = threadIdx.x, lane = tid & 31, wid = tid >> 5;
    int wm = wid & 1, wn = wid >> 1;

    const __half* gsrc[8];
    uint32_t sdst[8];
#pragma unroll
    for (int ci = 0; ci < 2; ci++) {
        int c = tid + ci * 256;
        int row = c >> 2, kc = c & 3;
        int tok = g_slot_token[e * CAP + m0 + row] & (NTOK - 1);
        size_t ar = (size_t)tok * IN_D + kc * 8;
        size_t br = ((size_t)e * HD + n0 + row) * IN_D + kc * 8;
        gsrc[ci * 4 + 0] = g_xh + ar;
        gsrc[ci * 4 + 1] = g_xl + ar;
        gsrc[ci * 4 + 2] = g_w1h + br;
        gsrc[ci * 4 + 3] = g_wgh + br;
        uint32_t sd = sb + row * LDSROW + kc * 16;
#pragma unroll
        for (int comp = 0; comp < 4; comp++) sdst[ci * 4 + comp] = sd + comp * CSZ;
    }

    const int STG = 4 * CSZ;   // 40960 per stage, 4 slots
    auto load_stage = [&](int slab, int st) {
        int ko = slab * 32;
        uint32_t so = st * STG;
#pragma unroll
        for (int i = 0; i < 8; i++) CPA16(sdst[i] + so, gsrc[i] + ko);
        asm volatile("cp.async.commit_group;" ::: "memory");
    };
    load_stage(0, 0);
    load_stage(1, 1);
    load_stage(2, 2);

    uint32_t a_off[4], b_off[2];
#pragma unroll
    for (int mi = 0; mi < 4; mi++)
        a_off[mi] = (wm * 64 + mi * 16 + (lane & 15)) * LDSROW + (lane >> 4) * 16;
#pragma unroll
    for (int ni = 0; ni < 2; ni++)
        b_off[ni] = (wn * 32 + ni * 16 + (lane & 7) + ((lane >> 4) << 3)) * LDSROW
                    + ((lane >> 3) & 1) * 16;

    float acc1[4][4][4], acc2[4][4][4];
#pragma unroll
    for (int mi = 0; mi < 4; mi++)
#pragma unroll
        for (int nj = 0; nj < 4; nj++)
#pragma unroll
            for (int q = 0; q < 4; q++) { acc1[mi][nj][q] = 0.f; acc2[mi][nj][q] = 0.f; }

    for (int s = 0; s < 32; s++) {
        int st = s & 3;
        if (s < 29) asm volatile("cp.async.wait_group 2;" ::: "memory");
        else        asm volatile("cp.async.wait_group 0;" ::: "memory");
        __syncthreads();
        // prefetch into slot (s+3)&3 == (s-1)&3: consumed last iter, barrier-ordered
        if (s < 29) load_stage(s + 3, (s + 3) & 3);
        uint32_t base = sb + st * STG;
#pragma unroll
        for (int ks = 0; ks < 2; ks++) {
            uint32_t kb = ks * 32;
            uint32_t Ah[4][4], Al[4][4], B1[2][4], B2[2][4];
#pragma unroll
            for (int mi = 0; mi < 4; mi++) LDSM4(Ah[mi], base + a_off[mi] + kb);
#pragma unroll
            for (int mi = 0; mi < 4; mi++) LDSM4(Al[mi], base + CSZ + a_off[mi] + kb);
#pragma unroll
            for (int ni = 0; ni < 2; ni++) LDSM4(B1[ni], base + 2 * CSZ + b_off[ni] + kb);
#pragma unroll
            for (int ni = 0; ni < 2; ni++) LDSM4(B2[ni], base + 3 * CSZ + b_off[ni] + kb);
#pragma unroll
            for (int mi = 0; mi < 4; mi++)
#pragma unroll
                for (int ni = 0; ni < 2; ni++)
#pragma unroll
                    for (int hh = 0; hh < 2; hh++) {
                        int nj = ni * 2 + hh;
                        MMA_F16(acc1[mi][nj], Ah[mi], B1[ni] + hh * 2);
                        MMA_F16(acc1[mi][nj], Al[mi], B1[ni] + hh * 2);
                        MMA_F16(acc2[mi][nj], Ah[mi], B2[ni] + hh * 2);
                        MMA_F16(acc2[mi][nj], Al[mi], B2[ni] + hh * 2);
                    }
        }
    }

    // --- SwiGLU epilogue, write h as fp16 (hi only) ---
#pragma unroll
    for (int mi = 0; mi < 4; mi++) {
        int rbase = m0 + wm * 64 + mi * 16 + (lane >> 2);
#pragma unroll
        for (int rr = 0; rr < 2; rr++) {
            int r = rbase + rr * 8;
            if (r < kept) {
                size_t ro = (size_t)(e * CAP + r) * HD;
#pragma unroll
                for (int nj = 0; nj < 4; nj++) {
                    int col = n0 + wn * 32 + nj * 8 + (lane & 3) * 2;
                    float v0 = acc1[mi][nj][rr * 2 + 0], v1 = acc1[mi][nj][rr * 2 + 1];
                    float g0 = acc2[mi][nj][rr * 2 + 0], g1 = acc2[mi][nj][rr * 2 + 1];
                    float h0 = v0 / (1.f + __expf(-v0)) * g0;
                    float h1 = v1 / (1.f + __expf(-v1)) * g1;
                    *(__half2*)(g_hh + ro + col) =
                        __halves2half2(__float2half_rn(h0), __float2half_rn(h1));
                }
            }
        }
    }
}

// ============================================================
// 5) GEMM2: out = H . fc2^T, K = 2048
//    comps per stage: [hh, w2] -> 4 slots, 2 CTAs/SM
// ============================================================
__global__ __launch_bounds__(256, 2) void gemm2_mma()
{
    extern __shared__ char smem[];
    int e = blockIdx.z;
    int kept = g_kept[e];
    int m0 = blockIdx.x * 128;
    if (m0 >= kept) return;
    int n0 = blockIdx.y * 128;

    uint32_t sb = smem_u32(smem);
    int tid = threadIdx.x, lane = tid & 31, wid = tid >> 5;
    int wm = wid & 1, wn = wid >> 1;

    const __half* gsrc[4];
    uint32_t sdst[4];
#pragma unroll
    for (int ci = 0; ci < 2; ci++) {
        int c = tid + ci * 256;
        int row = c >> 2, kc = c & 3;
        size_t ar = (size_t)(e * CAP + m0 + row) * HD + kc * 8;
        size_t br = ((size_t)e * IN_D + n0 + row) * HD + kc * 8;
        gsrc[ci * 2 + 0] = g_hh + ar;
        gsrc[ci * 2 + 1] = g_w2h + br;
        uint32_t sd = sb + row * LDSROW + kc * 16;
#pragma unroll
        for (int comp = 0; comp < 2; comp++) sdst[ci * 2 + comp] = sd + comp * CSZ;
    }

    const int STG = 2 * CSZ;   // 20480 per stage, 4 slots = 81920
    auto load_stage = [&](int slab, int st) {
        int ko = slab * 32;
        uint32_t so = st * STG;
#pragma unroll
        for (int i = 0; i < 4; i++) CPA16(sdst[i] + so, gsrc[i] + ko);
        asm volatile("cp.async.commit_group;" ::: "memory");
    };
    load_stage(0, 0);
    load_stage(1, 1);
    load_stage(2, 2);

    uint32_t a_off[4], b_off[2];
#pragma unroll
    for (int mi = 0; mi < 4; mi++)
        a_off[mi] = (wm * 64 + mi * 16 + (lane & 15)) * LDSROW + (lane >> 4) * 16;
#pragma unroll
    for (int ni = 0; ni < 2; ni++)
        b_off[ni] = (wn * 32 + ni * 16 + (lane & 7) + ((lane >> 4) << 3)) * LDSROW
                    + ((lane >> 3) & 1) * 16;

    float acc[4][4][4];
#pragma unroll
    for (int mi = 0; mi < 4; mi++)
#pragma unroll
        for (int nj = 0; nj < 4; nj++)
#pragma unroll
            for (int q = 0; q < 4; q++) acc[mi][nj][q] = 0.f;

    for (int s = 0; s < 64; s++) {
        int st = s & 3;
        if (s < 61) asm volatile("cp.async.wait_group 2;" ::: "memory");
        else        asm volatile("cp.async.wait_group 0;" ::: "memory");
        __syncthreads();
        if (s < 61) load_stage(s + 3, (s + 3) & 3);
        uint32_t base = sb + st * STG;
#pragma unroll
        for (int ks = 0; ks < 2; ks++) {
            uint32_t kb = ks * 32;
            uint32_t Ah[4][4], B[2][4];
#pragma unroll
            for (int mi = 0; mi < 4; mi++) LDSM4(Ah[mi], base + a_off[mi] + kb);
#pragma unroll
            for (int ni = 0; ni < 2; ni++) LDSM4(B[ni], base + CSZ + b_off[ni] + kb);
#pragma unroll
            for (int mi = 0; mi < 4; mi++)
#pragma unroll
                for (int ni = 0; ni < 2; ni++)
#pragma unroll
                    for (int hh = 0; hh < 2; hh++)
                        MMA_F16(acc[mi][ni * 2 + hh], Ah[mi], B[ni] + hh * 2);
        }
    }

#pragma unroll
    for (int mi = 0; mi < 4; mi++) {
        int rbase = m0 + wm * 64 + mi * 16 + (lane >> 2);
#pragma unroll
        for (int rr = 0; rr < 2; rr++) {
            int r = rbase + rr * 8;
            if (r < kept) {
                size_t ro = (size_t)(e * CAP + r) * IN_D;
#pragma unroll
                for (int nj = 0; nj < 4; nj++) {
                    int col = n0 + wn * 32 + nj * 8 + (lane & 3) * 2;
                    float2 v;
                    v.x = acc[mi][nj][rr * 2 + 0];
                    v.y = acc[mi][nj][rr * 2 + 1];
                    *(float2*)(g_buf_out + ro + col) = v;
                }
            }
        }
    }
}

// ============================================================
// 6) combine
// ============================================================
__global__ __launch_bounds__(256) void combine_kernel(float* __restrict__ out)
{
    int t = blockIdx.x;
    int s1 = g_slot[2 * t];
    int s2 = g_slot[2 * t + 1];
    float w1 = (s1 >= 0) ? g_w[2 * t] : 0.f;
    float w2 = (s2 >= 0) ? g_w[2 * t + 1] : 0.f;
    const float4* r1 = (s1 >= 0) ? (const float4*)(g_buf_out + (size_t)s1 * IN_D) : nullptr;
    const float4* r2 = (s2 >= 0) ? (const float4*)(g_buf_out + (size_t)s2 * IN_D) : nullptr;

    int d = threadIdx.x;
    float4 v = make_float4(0, 0, 0, 0);
    if (r1) {
        float4 a = r1[d];
        v.x += w1 * a.x; v.y += w1 * a.y; v.z += w1 * a.z; v.w += w1 * a.w;
    }
    if (r2) {
        float4 a = r2[d];
        v.x += w2 * a.x; v.y += w2 * a.y; v.z += w2 * a.z; v.w += w2 * a.w;
    }
    ((float4*)(out + (size_t)t * IN_D))[d] = v;
}

// ============================================================
extern "C" void kernel_launch(void* const* d_in, const int* in_sizes, int n_in,
                              void* d_out, int out_size)
{
    const float* x      = (const float*)d_in[0];
    const float* gate_w = (const float*)d_in[1];
    const float* fc1_w  = (const float*)d_in[2];
    const float* gating = (const float*)d_in[3];
    const float* fc2_w  = (const float*)d_in[4];
    float* out = (float*)d_out;
    float* loss_ptr = (out_size > NTOK * IN_D) ? out + (size_t)NTOK * IN_D : nullptr;

    const int smem1 = 4 * 4 * CSZ;   // 163840
    const int smem2 = 4 * 2 * CSZ;   // 81920  (2 CTAs/SM)
    cudaFuncSetAttribute(gemm1_mma, cudaFuncAttributeMaxDynamicSharedMemorySize, smem1);
    cudaFuncSetAttribute(gemm2_mma, cudaFuncAttributeMaxDynamicSharedMemorySize, smem2);

    const int n4 = NTOK * IN_D / 4;
    split_x_kernel<<<2048, 256>>>((const float4*)x, n4);
    conv_w_kernel<<<2048, 256>>>((const float4*)fc1_w,  1, n4);
    conv_w_kernel<<<2048, 256>>>((const float4*)gating, 2, n4);
    conv_w_kernel<<<2048, 256>>>((const float4*)fc2_w,  3, n4);

    route_kernel<<<ROUTE_BLOCKS, 256>>>(x, gate_w);
    dispatch_kernel<<<1, 1024>>>();
    loss_kernel<<<1, 32>>>(loss_ptr);
    gemm1_mma<<<dim3(CAP / 128, HD / 128, E_NUM), 256, smem1>>>();
    gemm2_mma<<<dim3(CAP / 128, IN_D / 128, E_NUM), 256, smem2>>>();
    combine_kernel<<<NTOK, 256>>>(out);
}

// round 9
// speedup vs baseline: 5.1250x; 1.3367x over previous
#include <cuda_runtime.h>
#include <cuda_bf16.h>
#include <cuda_fp16.h>
#include <cstdint>
#include <math.h>

// ---------------- problem constants ----------------
#define E_NUM      8
#define TOPK       2
#define IN_D       1024
#define HD         2048
#define NTOK       16384
#define NK         32768
#define CAP        5120
#define ROUTE_BLOCKS 2048

// ---------------- device scratch ----------------
__device__ __half g_xh[(size_t)NTOK * IN_D];
__device__ __half g_w1h[(size_t)E_NUM * HD * IN_D];
__device__ __half g_wgh[(size_t)E_NUM * HD * IN_D];
__device__ __half g_w2h[(size_t)E_NUM * IN_D * HD];
__device__ __half g_hh[(size_t)E_NUM * CAP * HD];
__device__ float g_buf_out[(size_t)E_NUM * CAP * IN_D];
__device__ int   g_exp[NK];
__device__ float g_w[NK];
__device__ int   g_slot[NK];
__device__ int   g_slot_token[E_NUM * CAP];
__device__ int   g_counts[E_NUM];
__device__ int   g_kept[E_NUM];
__device__ float g_prob_part[ROUTE_BLOCKS * E_NUM];

// ---------------- PTX helpers ----------------
__device__ __forceinline__ uint32_t smem_u32(const void* p) {
    uint32_t a;
    asm("{ .reg .u64 t; cvta.to.shared.u64 t, %1; cvt.u32.u64 %0, t; }" : "=r"(a) : "l"(p));
    return a;
}

#define CPA16(dst, src) \
    asm volatile("cp.async.cg.shared.global [%0], [%1], 16;" :: "r"(dst), "l"(src) : "memory")

#define LDSM4(r, addr) \
    asm volatile("ldmatrix.sync.aligned.m8n8.x4.shared.b16 {%0,%1,%2,%3}, [%4];" \
        : "=r"((r)[0]), "=r"((r)[1]), "=r"((r)[2]), "=r"((r)[3]) : "r"(addr))

#define MMA_F16(d, a, bb) \
    asm volatile("mma.sync.aligned.m16n8k16.row.col.f32.f16.f16.f32 " \
        "{%0,%1,%2,%3}, {%4,%5,%6,%7}, {%8,%9}, {%0,%1,%2,%3};" \
        : "+f"((d)[0]), "+f"((d)[1]), "+f"((d)[2]), "+f"((d)[3]) \
        : "r"((a)[0]), "r"((a)[1]), "r"((a)[2]), "r"((a)[3]), \
          "r"((bb)[0]), "r"((bb)[1]))

// ============================================================
// 0) fp32 -> fp16 convert (x and all weights)
// ============================================================
__global__ __launch_bounds__(256) void conv_w_kernel(const float4* __restrict__ in,
                                                     int which, int n4)
{
    __half* dst;
    switch (which) {
        case 0: dst = g_xh;  break;
        case 1: dst = g_w1h; break;
        case 2: dst = g_wgh; break;
        default: dst = g_w2h; break;
    }
    uint2* d4 = (uint2*)dst;
    for (int i = blockIdx.x * blockDim.x + threadIdx.x; i < n4;
         i += gridDim.x * blockDim.x) {
        float4 v = in[i];
        __half2 h01 = __halves2half2(__float2half_rn(v.x), __float2half_rn(v.y));
        __half2 h23 = __halves2half2(__float2half_rn(v.z), __float2half_rn(v.w));
        uint2 o;
        o.x = *reinterpret_cast<uint32_t*>(&h01);
        o.y = *reinterpret_cast<uint32_t*>(&h23);
        d4[i] = o;
    }
}

// ============================================================
// 1) routing
// ============================================================
__global__ __launch_bounds__(256) void route_kernel(const float* __restrict__ x,
                                                    const float* __restrict__ gate_w)
{
    __shared__ float sg[E_NUM * IN_D];
    __shared__ float pp[8][E_NUM];
    for (int i = threadIdx.x; i < E_NUM * IN_D; i += blockDim.x) sg[i] = gate_w[i];
    __syncthreads();

    int w = threadIdx.x >> 5, lane = threadIdx.x & 31;
    int t = blockIdx.x * 8 + w;
    const float* xr = x + (size_t)t * IN_D;
    float acc[E_NUM];
#pragma unroll
    for (int e = 0; e < E_NUM; e++) acc[e] = 0.f;
    for (int j = 0; j < IN_D / 32; j++) {
        float xv = xr[lane + j * 32];
#pragma unroll
        for (int e = 0; e < E_NUM; e++) acc[e] += xv * sg[e * IN_D + lane + j * 32];
    }
#pragma unroll
    for (int off = 16; off > 0; off >>= 1)
#pragma unroll
        for (int e = 0; e < E_NUM; e++) acc[e] += __shfl_down_sync(0xffffffffu, acc[e], off);

    if (lane == 0) {
        float m = acc[0];
#pragma unroll
        for (int e = 1; e < E_NUM; e++) m = fmaxf(m, acc[e]);
        float p[E_NUM], s = 0.f;
#pragma unroll
        for (int e = 0; e < E_NUM; e++) { p[e] = expf(acc[e] - m); s += p[e]; }
        float inv = 1.f / s;
#pragma unroll
        for (int e = 0; e < E_NUM; e++) p[e] *= inv;
        int e1 = 0;
#pragma unroll
        for (int e = 1; e < E_NUM; e++) if (p[e] > p[e1]) e1 = e;
        int e2 = (e1 == 0) ? 1 : 0;
#pragma unroll
        for (int e = 0; e < E_NUM; e++) if (e != e1 && p[e] > p[e2]) e2 = e;
        float denom = p[e1] + p[e2] + 1e-9f;
        g_exp[2 * t] = e1; g_exp[2 * t + 1] = e2;
        g_w[2 * t] = p[e1] / denom; g_w[2 * t + 1] = p[e2] / denom;
#pragma unroll
        for (int e = 0; e < E_NUM; e++) pp[w][e] = p[e];
    }
    __syncthreads();
    if (threadIdx.x < E_NUM) {
        float s = 0.f;
        for (int ww = 0; ww < 8; ww++) s += pp[ww][threadIdx.x];
        g_prob_part[blockIdx.x * E_NUM + threadIdx.x] = s;
    }
}

// ============================================================
// 2) dispatch
// ============================================================
__global__ __launch_bounds__(1024) void dispatch_kernel()
{
    __shared__ int sc[1024 * E_NUM];
    int tid = threadIdx.x, base = tid * 32;
    int h[E_NUM];
#pragma unroll
    for (int e = 0; e < E_NUM; e++) h[e] = 0;
    for (int i = 0; i < 32; i++) h[g_exp[base + i]]++;
#pragma unroll
    for (int e = 0; e < E_NUM; e++) sc[tid * E_NUM + e] = h[e];
    __syncthreads();
    for (int off = 1; off < 1024; off <<= 1) {
        int v[E_NUM];
        if (tid >= off)
#pragma unroll
            for (int e = 0; e < E_NUM; e++) v[e] = sc[(tid - off) * E_NUM + e];
        __syncthreads();
        if (tid >= off)
#pragma unroll
            for (int e = 0; e < E_NUM; e++) sc[tid * E_NUM + e] += v[e];
        __syncthreads();
    }
    int basec[E_NUM];
#pragma unroll
    for (int e = 0; e < E_NUM; e++) basec[e] = sc[tid * E_NUM + e] - h[e];
    if (tid == 1023)
#pragma unroll
        for (int e = 0; e < E_NUM; e++) {
            int c = sc[tid * E_NUM + e];
            g_counts[e] = c;
            g_kept[e] = (c < CAP) ? c : CAP;
        }
    for (int i = 0; i < 32; i++) {
        int idx = base + i;
        int e = g_exp[idx];
        int pos = basec[e]++;
        if (pos < CAP) {
            int s = e * CAP + pos;
            g_slot[idx] = s;
            g_slot_token[s] = idx >> 1;
        } else g_slot[idx] = -1;
    }
}

// ============================================================
// 3) loss
// ============================================================
__global__ void loss_kernel(float* out_loss)
{
    __shared__ float ps[E_NUM];
    if (threadIdx.x < E_NUM) {
        float s = 0.f;
        for (int b = 0; b < ROUTE_BLOCKS; b++) s += g_prob_part[b * E_NUM + threadIdx.x];
        float p = s / (float)NTOK;
        float f = (float)g_counts[threadIdx.x] / (float)NK;
        ps[threadIdx.x] = p * f;
    }
    __syncthreads();
    if (threadIdx.x == 0 && out_loss) {
        float s = 0.f;
#pragma unroll
        for (int e = 0; e < E_NUM; e++) s += ps[e];
        *out_loss = (float)E_NUM * s;
    }
}

// ============================================================
// GEMM tiling: 128x128 tile, BK=32, 8 warps (64x32 warp tile)
// smem rows padded to 80B (conflict-free ldmatrix)
// Single-barrier pipeline: depth-3 prefetch over 4 slots
// Pure fp16 HMMA: 1 MMA per logical MAC
// ============================================================
#define LDSROW 80
#define CSZ    (128 * LDSROW)   // 10240 B per component tile

// ============================================================
// 4) GEMM1: h = silu(Xg . fc1^T) * (Xg . gating^T), K = 1024
//    comps per stage: [xh, w1, wg]
// ============================================================
__global__ __launch_bounds__(256, 1) void gemm1_mma()
{
    extern __shared__ char smem[];
    int e = blockIdx.z;
    int kept = g_kept[e];
    int m0 = blockIdx.x * 128;
    if (m0 >= kept) return;
    int n0 = blockIdx.y * 128;

    uint32_t sb = smem_u32(smem);
    int tid = threadIdx.x, lane = tid & 31, wid = tid >> 5;
    int wm = wid & 1, wn = wid >> 1;

    const __half* gsrc[6];
    uint32_t sdst[6];
#pragma unroll
    for (int ci = 0; ci < 2; ci++) {
        int c = tid + ci * 256;
        int row = c >> 2, kc = c & 3;
        int tok = g_slot_token[e * CAP + m0 + row] & (NTOK - 1);
        size_t ar = (size_t)tok * IN_D + kc * 8;
        size_t br = ((size_t)e * HD + n0 + row) * IN_D + kc * 8;
        gsrc[ci * 3 + 0] = g_xh + ar;
        gsrc[ci * 3 + 1] = g_w1h + br;
        gsrc[ci * 3 + 2] = g_wgh + br;
        uint32_t sd = sb + row * LDSROW + kc * 16;
#pragma unroll
        for (int comp = 0; comp < 3; comp++) sdst[ci * 3 + comp] = sd + comp * CSZ;
    }

    const int STG = 3 * CSZ;   // 30720 per stage, 4 slots = 122880
    auto load_stage = [&](int slab, int st) {
        int ko = slab * 32;
        uint32_t so = st * STG;
#pragma unroll
        for (int i = 0; i < 6; i++) CPA16(sdst[i] + so, gsrc[i] + ko);
        asm volatile("cp.async.commit_group;" ::: "memory");
    };
    load_stage(0, 0);
    load_stage(1, 1);
    load_stage(2, 2);

    uint32_t a_off[4], b_off[2];
#pragma unroll
    for (int mi = 0; mi < 4; mi++)
        a_off[mi] = (wm * 64 + mi * 16 + (lane & 15)) * LDSROW + (lane >> 4) * 16;
#pragma unroll
    for (int ni = 0; ni < 2; ni++)
        b_off[ni] = (wn * 32 + ni * 16 + (lane & 7) + ((lane >> 4) << 3)) * LDSROW
                    + ((lane >> 3) & 1) * 16;

    float acc1[4][4][4], acc2[4][4][4];
#pragma unroll
    for (int mi = 0; mi < 4; mi++)
#pragma unroll
        for (int nj = 0; nj < 4; nj++)
#pragma unroll
            for (int q = 0; q < 4; q++) { acc1[mi][nj][q] = 0.f; acc2[mi][nj][q] = 0.f; }

    for (int s = 0; s < 32; s++) {
        int st = s & 3;
        if (s < 29) asm volatile("cp.async.wait_group 2;" ::: "memory");
        else        asm volatile("cp.async.wait_group 0;" ::: "memory");
        __syncthreads();
        // prefetch into slot (s+3)&3 == (s-1)&3: consumed last iter, barrier-ordered
        if (s < 29) load_stage(s + 3, (s + 3) & 3);
        uint32_t base = sb + st * STG;
#pragma unroll
        for (int ks = 0; ks < 2; ks++) {
            uint32_t kb = ks * 32;
            uint32_t Ah[4][4], B1[2][4], B2[2][4];
#pragma unroll
            for (int mi = 0; mi < 4; mi++) LDSM4(Ah[mi], base + a_off[mi] + kb);
#pragma unroll
            for (int ni = 0; ni < 2; ni++) LDSM4(B1[ni], base + CSZ + b_off[ni] + kb);
#pragma unroll
            for (int ni = 0; ni < 2; ni++) LDSM4(B2[ni], base + 2 * CSZ + b_off[ni] + kb);
#pragma unroll
            for (int mi = 0; mi < 4; mi++)
#pragma unroll
                for (int ni = 0; ni < 2; ni++)
#pragma unroll
                    for (int hh = 0; hh < 2; hh++) {
                        int nj = ni * 2 + hh;
                        MMA_F16(acc1[mi][nj], Ah[mi], B1[ni] + hh * 2);
                        MMA_F16(acc2[mi][nj], Ah[mi], B2[ni] + hh * 2);
                    }
        }
    }

    // --- SwiGLU epilogue, write h as fp16 ---
#pragma unroll
    for (int mi = 0; mi < 4; mi++) {
        int rbase = m0 + wm * 64 + mi * 16 + (lane >> 2);
#pragma unroll
        for (int rr = 0; rr < 2; rr++) {
            int r = rbase + rr * 8;
            if (r < kept) {
                size_t ro = (size_t)(e * CAP + r) * HD;
#pragma unroll
                for (int nj = 0; nj < 4; nj++) {
                    int col = n0 + wn * 32 + nj * 8 + (lane & 3) * 2;
                    float v0 = acc1[mi][nj][rr * 2 + 0], v1 = acc1[mi][nj][rr * 2 + 1];
                    float g0 = acc2[mi][nj][rr * 2 + 0], g1 = acc2[mi][nj][rr * 2 + 1];
                    float h0 = v0 / (1.f + __expf(-v0)) * g0;
                    float h1 = v1 / (1.f + __expf(-v1)) * g1;
                    *(__half2*)(g_hh + ro + col) =
                        __halves2half2(__float2half_rn(h0), __float2half_rn(h1));
                }
            }
        }
    }
}

// ============================================================
// 5) GEMM2: out = H . fc2^T, K = 2048
//    comps per stage: [hh, w2] -> 4 slots, 2 CTAs/SM
// ============================================================
__global__ __launch_bounds__(256, 2) void gemm2_mma()
{
    extern __shared__ char smem[];
    int e = blockIdx.z;
    int kept = g_kept[e];
    int m0 = blockIdx.x * 128;
    if (m0 >= kept) return;
    int n0 = blockIdx.y * 128;

    uint32_t sb = smem_u32(smem);
    int tid = threadIdx.x, lane = tid & 31, wid = tid >> 5;
    int wm = wid & 1, wn = wid >> 1;

    const __half* gsrc[4];
    uint32_t sdst[4];
#pragma unroll
    for (int ci = 0; ci < 2; ci++) {
        int c = tid + ci * 256;
        int row = c >> 2, kc = c & 3;
        size_t ar = (size_t)(e * CAP + m0 + row) * HD + kc * 8;
        size_t br = ((size_t)e * IN_D + n0 + row) * HD + kc * 8;
        gsrc[ci * 2 + 0] = g_hh + ar;
        gsrc[ci * 2 + 1] = g_w2h + br;
        uint32_t sd = sb + row * LDSROW + kc * 16;
#pragma unroll
        for (int comp = 0; comp < 2; comp++) sdst[ci * 2 + comp] = sd + comp * CSZ;
    }

    const int STG = 2 * CSZ;   // 20480 per stage, 4 slots = 81920
    auto load_stage = [&](int slab, int st) {
        int ko = slab * 32;
        uint32_t so = st * STG;
#pragma unroll
        for (int i = 0; i < 4; i++) CPA16(sdst[i] + so, gsrc[i] + ko);
        asm volatile("cp.async.commit_group;" ::: "memory");
    };
    load_stage(0, 0);
    load_stage(1, 1);
    load_stage(2, 2);

    uint32_t a_off[4], b_off[2];
#pragma unroll
    for (int mi = 0; mi < 4; mi++)
        a_off[mi] = (wm * 64 + mi * 16 + (lane & 15)) * LDSROW + (lane >> 4) * 16;
#pragma unroll
    for (int ni = 0; ni < 2; ni++)
        b_off[ni] = (wn * 32 + ni * 16 + (lane & 7) + ((lane >> 4) << 3)) * LDSROW
                    + ((lane >> 3) & 1) * 16;

    float acc[4][4][4];
#pragma unroll
    for (int mi = 0; mi < 4; mi++)
#pragma unroll
        for (int nj = 0; nj < 4; nj++)
#pragma unroll
            for (int q = 0; q < 4; q++) acc[mi][nj][q] = 0.f;

    for (int s = 0; s < 64; s++) {
        int st = s & 3;
        if (s < 61) asm volatile("cp.async.wait_group 2;" ::: "memory");
        else        asm volatile("cp.async.wait_group 0;" ::: "memory");
        __syncthreads();
        if (s < 61) load_stage(s + 3, (s + 3) & 3);
        uint32_t base = sb + st * STG;
#pragma unroll
        for (int ks = 0; ks < 2; ks++) {
            uint32_t kb = ks * 32;
            uint32_t Ah[4][4], B[2][4];
#pragma unroll
            for (int mi = 0; mi < 4; mi++) LDSM4(Ah[mi], base + a_off[mi] + kb);
#pragma unroll
            for (int ni = 0; ni < 2; ni++) LDSM4(B[ni], base + CSZ + b_off[ni] + kb);
#pragma unroll
            for (int mi = 0; mi < 4; mi++)
#pragma unroll
                for (int ni = 0; ni < 2; ni++)
#pragma unroll
                    for (int hh = 0; hh < 2; hh++)
                        MMA_F16(acc[mi][ni * 2 + hh], Ah[mi], B[ni] + hh * 2);
        }
    }

#pragma unroll
    for (int mi = 0; mi < 4; mi++) {
        int rbase = m0 + wm * 64 + mi * 16 + (lane >> 2);
#pragma unroll
        for (int rr = 0; rr < 2; rr++) {
            int r = rbase + rr * 8;
            if (r < kept) {
                size_t ro = (size_t)(e * CAP + r) * IN_D;
#pragma unroll
                for (int nj = 0; nj < 4; nj++) {
                    int col = n0 + wn * 32 + nj * 8 + (lane & 3) * 2;
                    float2 v;
                    v.x = acc[mi][nj][rr * 2 + 0];
                    v.y = acc[mi][nj][rr * 2 + 1];
                    *(float2*)(g_buf_out + ro + col) = v;
                }
            }
        }
    }
}

// ============================================================
// 6) combine
// ============================================================
__global__ __launch_bounds__(256) void combine_kernel(float* __restrict__ out)
{
    int t = blockIdx.x;
    int s1 = g_slot[2 * t];
    int s2 = g_slot[2 * t + 1];
    float w1 = (s1 >= 0) ? g_w[2 * t] : 0.f;
    float w2 = (s2 >= 0) ? g_w[2 * t + 1] : 0.f;
    const float4* r1 = (s1 >= 0) ? (const float4*)(g_buf_out + (size_t)s1 * IN_D) : nullptr;
    const float4* r2 = (s2 >= 0) ? (const float4*)(g_buf_out + (size_t)s2 * IN_D) : nullptr;

    int d = threadIdx.x;
    float4 v = make_float4(0, 0, 0, 0);
    if (r1) {
        float4 a = r1[d];
        v.x += w1 * a.x; v.y += w1 * a.y; v.z += w1 * a.z; v.w += w1 * a.w;
    }
    if (r2) {
        float4 a = r2[d];
        v.x += w2 * a.x; v.y += w2 * a.y; v.z += w2 * a.z; v.w += w2 * a.w;
    }
    ((float4*)(out + (size_t)t * IN_D))[d] = v;
}

// ============================================================
extern "C" void kernel_launch(void* const* d_in, const int* in_sizes, int n_in,
                              void* d_out, int out_size)
{
    const float* x      = (const float*)d_in[0];
    const float* gate_w = (const float*)d_in[1];
    const float* fc1_w  = (const float*)d_in[2];
    const float* gating = (const float*)d_in[3];
    const float* fc2_w  = (const float*)d_in[4];
    float* out = (float*)d_out;
    float* loss_ptr = (out_size > NTOK * IN_D) ? out + (size_t)NTOK * IN_D : nullptr;

    const int smem1 = 4 * 3 * CSZ;   // 122880
    const int smem2 = 4 * 2 * CSZ;   // 81920  (2 CTAs/SM)
    cudaFuncSetAttribute(gemm1_mma, cudaFuncAttributeMaxDynamicSharedMemorySize, smem1);
    cudaFuncSetAttribute(gemm2_mma, cudaFuncAttributeMaxDynamicSharedMemorySize, smem2);

    const int n4 = NTOK * IN_D / 4;
    conv_w_kernel<<<2048, 256>>>((const float4*)x,      0, n4);
    conv_w_kernel<<<2048, 256>>>((const float4*)fc1_w,  1, n4);
    conv_w_kernel<<<2048, 256>>>((const float4*)gating, 2, n4);
    conv_w_kernel<<<2048, 256>>>((const float4*)fc2_w,  3, n4);

    route_kernel<<<ROUTE_BLOCKS, 256>>>(x, gate_w);
    dispatch_kernel<<<1, 1024>>>();
    loss_kernel<<<1, 32>>>(loss_ptr);
    gemm1_mma<<<dim3(CAP / 128, HD / 128, E_NUM), 256, smem1>>>();
    gemm2_mma<<<dim3(CAP / 128, IN_D / 128, E_NUM), 256, smem2>>>();
    combine_kernel<<<NTOK, 256>>>(out);
}